// round 2
// baseline (speedup 1.0000x reference)
#include <cuda_runtime.h>
#include <math.h>

#define NB   1024
#define TT   48
#define NA   35
#define NM   18
#define NN   53
#define HH   32
#define CTXD 60
#define THREADS 256
#define HS   33   // padded row stride to avoid bank conflicts

struct SM {
    float base[NN*NN];        // mask-folded adj_norm * a_last per (i,j)
    float e[NN*NN];           // attention logits -> probabilities
    float h[2][NN*HS];        // GRU hidden state, double buffered
    float featf[NN*HS];       // feat (f-part); reused as GAT output
    float attri[NN*HS];       // aggregation values
    float srcA[NN], srcM[NN], dstA[NN], dstM[NN];
    float ctxsA[NN], ctxsM[NN], ctxdA[NN], ctxdM[NN];
    float a_src_f[4][HH];
    float a_dst_f[4][HH];
    float a_last[4];
    float Wxa[6*HH], Wxm[4*HH], Wua[14*HH], Wum[14*HH];
    float wih_a[96*HS], whh_a[96*HS], wih_m[96*HS], whh_m[96*HS];
    float bih_a[96], bhh_a[96], bih_m[96], bhh_m[96];
    float emb_aqi[79*2];      // rows: id@0(35), month@35(13), weekday@48(7), hour@55(24)
    float emb_meo[71*2];      // rows: wind@0(9), id@9(18), month@27(13), weekday@40(7), hour@47(24)
    float xa[NA*6];
    float xm[NM*4];
    int   exa[NA*4];
    int   exm[NM*5];
};

__device__ __forceinline__ float sigmoidf_(float x) { return 1.f/(1.f+expf(-x)); }

__global__ __launch_bounds__(THREADS, 2)
void chgat_gru_kernel(
    const float* __restrict__ X_aqi, const float* __restrict__ X_meo,
    const float* __restrict__ ctx,   const float* __restrict__ adj,
    const float* __restrict__ adjn,
    const float* __restrict__ e_ai,  const float* __restrict__ e_amo,
    const float* __restrict__ e_awd, const float* __restrict__ e_ahr,
    const float* __restrict__ e_mw,  const float* __restrict__ e_mi,
    const float* __restrict__ e_mmo, const float* __restrict__ e_mwd,
    const float* __restrict__ e_mhr,
    const float* __restrict__ Wxa,   const float* __restrict__ Wxm,
    const float* __restrict__ Wua,   const float* __restrict__ Wum,
    const float* __restrict__ a_aa,  const float* __restrict__ a_am,
    const float* __restrict__ a_ma,  const float* __restrict__ a_mm,
    const float* __restrict__ gaw_ih, const float* __restrict__ gaw_hh,
    const float* __restrict__ gab_ih, const float* __restrict__ gab_hh,
    const float* __restrict__ gmw_ih, const float* __restrict__ gmw_hh,
    const float* __restrict__ gmb_ih, const float* __restrict__ gmb_hh,
    const int* __restrict__ Xa_ex,   const int* __restrict__ Xm_ex,
    float* __restrict__ out)
{
    extern __shared__ char smraw[];
    SM& s = *reinterpret_cast<SM*>(smraw);

    const int tid  = threadIdx.x;
    const int b    = blockIdx.x;
    const int lane = tid & 31;
    const int wid  = tid >> 5;

    // ---------- one-time setup: copy weights to smem ----------
    for (int i = tid; i < 6*HH;  i += THREADS) s.Wxa[i] = Wxa[i];
    for (int i = tid; i < 4*HH;  i += THREADS) s.Wxm[i] = Wxm[i];
    for (int i = tid; i < 14*HH; i += THREADS) { s.Wua[i] = Wua[i]; s.Wum[i] = Wum[i]; }
    for (int i = tid; i < 96*HH; i += THREADS) {
        int g = i >> 5, k = i & 31;
        s.wih_a[g*HS+k] = gaw_ih[i]; s.whh_a[g*HS+k] = gaw_hh[i];
        s.wih_m[g*HS+k] = gmw_ih[i]; s.whh_m[g*HS+k] = gmw_hh[i];
    }
    for (int i = tid; i < 96; i += THREADS) {
        s.bih_a[i] = gab_ih[i]; s.bhh_a[i] = gab_hh[i];
        s.bih_m[i] = gmb_ih[i]; s.bhh_m[i] = gmb_hh[i];
    }
    const float* avec0 = a_aa; const float* avec1 = a_am;
    const float* avec2 = a_ma; const float* avec3 = a_mm;
    for (int i = tid; i < 4*HH; i += THREADS) {
        int c = i >> 5, k = i & 31;
        const float* a = (c==0)?avec0:(c==1)?avec1:(c==2)?avec2:avec3;
        s.a_src_f[c][k] = a[k];
        s.a_dst_f[c][k] = a[92+k];
    }
    if (tid < 4) {
        const float* a = (tid==0)?avec0:(tid==1)?avec1:(tid==2)?avec2:avec3;
        s.a_last[tid] = a[184];
    }
    // embeddings (concatenated, offsets in floats)
    for (int i = tid; i < 70; i += THREADS) s.emb_aqi[i]      = e_ai[i];
    for (int i = tid; i < 26; i += THREADS) s.emb_aqi[70+i]   = e_amo[i];
    for (int i = tid; i < 14; i += THREADS) s.emb_aqi[96+i]   = e_awd[i];
    for (int i = tid; i < 48; i += THREADS) s.emb_aqi[110+i]  = e_ahr[i];
    for (int i = tid; i < 18; i += THREADS) s.emb_meo[i]      = e_mw[i];
    for (int i = tid; i < 36; i += THREADS) s.emb_meo[18+i]   = e_mi[i];
    for (int i = tid; i < 26; i += THREADS) s.emb_meo[54+i]   = e_mmo[i];
    for (int i = tid; i < 14; i += THREADS) s.emb_meo[80+i]   = e_mwd[i];
    for (int i = tid; i < 48; i += THREADS) s.emb_meo[94+i]   = e_mhr[i];
    // init hidden state
    for (int i = tid; i < NN*HS; i += THREADS) s.h[0][i] = 0.f;
    __syncthreads();

    // ---------- one-time: context contributions to src/dst ----------
    for (int p = tid; p < 4*NN; p += THREADS) {
        int n = p % NN, role = p / NN;
        int c; const float* w;
        if (role == 0)      { c = (n<NA)?0:2; }
        else if (role == 1) { c = (n<NA)?1:3; }
        else if (role == 2) { c = (n<NA)?0:1; }
        else                { c = (n<NA)?2:3; }
        const float* a = (c==0)?avec0:(c==1)?avec1:(c==2)?avec2:avec3;
        w = (role < 2) ? (a + 32) : (a + 124);
        float acc = 0.f;
        #pragma unroll 4
        for (int k = 0; k < CTXD; k++) acc += ctx[n*CTXD+k]*w[k];
        if (role == 0)      s.ctxsA[n] = acc;
        else if (role == 1) s.ctxsM[n] = acc;
        else if (role == 2) s.ctxdA[n] = acc;
        else                s.ctxdM[n] = acc;
    }
    // base matrix: mask folded in via -1e30 (exp underflows to exactly 0;
    // all-masked rows degenerate to uniform, matching the reference NEG path)
    for (int p = tid; p < NN*NN; p += THREADS) {
        int i = p / NN, j = p % NN;
        int c = ((i < NA) ? 0 : 2) + ((j < NA) ? 0 : 1);
        s.base[p] = (adj[p] > 0.f) ? adjn[p]*s.a_last[c] : -1e30f;
    }
    __syncthreads();

    // ---------- timestep loop ----------
    for (int t = 0; t < TT; t++) {
        // phase 0: load this step's raw features + index features
        {
            const float* gx = X_aqi + (size_t)(b*TT + t)*NA*6;
            for (int i = tid; i < NA*6; i += THREADS) s.xa[i] = gx[i];
            const float* gm = X_meo + (size_t)(b*TT + t)*NM*4;
            for (int i = tid; i < NM*4; i += THREADS) s.xm[i] = gm[i];
            const int* ga = Xa_ex + (size_t)(b*TT + t)*NA*4;
            for (int i = tid; i < NA*4; i += THREADS) s.exa[i] = ga[i];
            const int* gme = Xm_ex + (size_t)(b*TT + t)*NM*5;
            for (int i = tid; i < NM*5; i += THREADS) s.exm[i] = gme[i];
        }
        __syncthreads();

        // phase 1: attri + featf  (53*32 jobs)
        for (int p = tid; p < NN*HH; p += THREADS) {
            int n = p >> 5, hd = p & 31;
            float av = 0.f, fv = 0.f;
            if (n < NA) {
                #pragma unroll
                for (int k = 0; k < 6; k++) {
                    float x = s.xa[n*6+k];
                    av += x * s.Wxa[k*HH+hd];
                    fv += x * s.Wua[k*HH+hd];
                }
                const int offs[4] = {0, 35, 48, 55};
                #pragma unroll
                for (int e4 = 0; e4 < 4; e4++) {
                    int row = offs[e4] + s.exa[n*4+e4];
                    fv += s.emb_aqi[row*2+0]*s.Wua[(6+2*e4)*HH+hd]
                        + s.emb_aqi[row*2+1]*s.Wua[(7+2*e4)*HH+hd];
                }
            } else {
                int m = n - NA;
                #pragma unroll
                for (int k = 0; k < 4; k++) {
                    float x = s.xm[m*4+k];
                    av += x * s.Wxm[k*HH+hd];
                    fv += x * s.Wum[k*HH+hd];
                }
                const int offs[5] = {0, 9, 27, 40, 47};
                #pragma unroll
                for (int e5 = 0; e5 < 5; e5++) {
                    int row = offs[e5] + s.exm[m*5+e5];
                    fv += s.emb_meo[row*2+0]*s.Wum[(4+2*e5)*HH+hd]
                        + s.emb_meo[row*2+1]*s.Wum[(5+2*e5)*HH+hd];
                }
            }
            s.attri[n*HS+hd] = av;
            s.featf[n*HS+hd] = fv;
        }
        __syncthreads();

        // phase 2: src/dst projections (4*53 dot-32 jobs)
        for (int p = tid; p < 4*NN; p += THREADS) {
            int n = p % NN, role = p / NN;
            int c; float acc; const float* w;
            if (role == 0)      { c = (n<NA)?0:2; w = s.a_src_f[c]; acc = s.ctxsA[n]; }
            else if (role == 1) { c = (n<NA)?1:3; w = s.a_src_f[c]; acc = s.ctxsM[n]; }
            else if (role == 2) { c = (n<NA)?0:1; w = s.a_dst_f[c]; acc = s.ctxdA[n]; }
            else                { c = (n<NA)?2:3; w = s.a_dst_f[c]; acc = s.ctxdM[n]; }
            const float* f = &s.featf[n*HS];
            #pragma unroll
            for (int k = 0; k < HH; k++) acc += f[k]*w[k];
            if (role == 0)      s.srcA[n] = acc;
            else if (role == 1) s.srcM[n] = acc;
            else if (role == 2) s.dstA[n] = acc;
            else                s.dstM[n] = acc;
        }
        __syncthreads();

        // phase 3: attention logits e[i][j] = leaky(src + dst + base)
        for (int p = tid; p < NN*NN; p += THREADS) {
            int i = p / NN, j = p % NN;
            float sv = (j < NA) ? s.srcA[i] : s.srcM[i];
            float dv = (i < NA) ? s.dstA[j] : s.dstM[j];
            float x = sv + dv + s.base[p];
            s.e[p] = (x >= 0.f) ? x : 0.2f*x;
        }
        __syncthreads();

        // phase 4: row softmax (warp per row)
        for (int r = wid; r < NN; r += (THREADS/32)) {
            float m = -3.0e38f;
            for (int j = lane; j < NN; j += 32) m = fmaxf(m, s.e[r*NN+j]);
            #pragma unroll
            for (int o = 16; o; o >>= 1) m = fmaxf(m, __shfl_xor_sync(0xffffffffu, m, o));
            float ssum = 0.f;
            for (int j = lane; j < NN; j += 32) {
                float v = expf(s.e[r*NN+j] - m);
                s.e[r*NN+j] = v;
                ssum += v;
            }
            #pragma unroll
            for (int o = 16; o; o >>= 1) ssum += __shfl_xor_sync(0xffffffffu, ssum, o);
            float inv = 1.f/ssum;
            for (int j = lane; j < NN; j += 32) s.e[r*NN+j] *= inv;
        }
        __syncthreads();

        // phase 5: out = att @ attri  (into featf buffer, featf no longer needed)
        for (int p = tid; p < NN*HH; p += THREADS) {
            int n = p >> 5, hd = p & 31;
            float acc = 0.f;
            const float* arow = &s.e[n*NN];
            #pragma unroll 4
            for (int j = 0; j < NN; j++) acc += arow[j]*s.attri[j*HS+hd];
            s.featf[n*HS+hd] = acc;   // overwrite: GAT output
        }
        __syncthreads();

        // phase 6: GRU update (per (node, dim))
        {
            const float* cur = s.h[t & 1];
            float*       nxt = s.h[(t+1) & 1];
            for (int p = tid; p < NN*HH; p += THREADS) {
                int n = p >> 5, hd = p & 31;
                const float *wih, *whh, *bih, *bhh;
                if (n < NA) { wih=s.wih_a; whh=s.whh_a; bih=s.bih_a; bhh=s.bhh_a; }
                else        { wih=s.wih_m; whh=s.whh_m; bih=s.bih_m; bhh=s.bhh_m; }
                const float* xv = &s.featf[n*HS];
                const float* hv = &cur[n*HS];
                float gir = bih[hd],    giz = bih[32+hd], gin = bih[64+hd];
                float ghr = bhh[hd],    ghz = bhh[32+hd], ghn = bhh[64+hd];
                const float* w0 = &wih[hd*HS];
                const float* w1 = &wih[(32+hd)*HS];
                const float* w2 = &wih[(64+hd)*HS];
                const float* v0 = &whh[hd*HS];
                const float* v1 = &whh[(32+hd)*HS];
                const float* v2 = &whh[(64+hd)*HS];
                #pragma unroll
                for (int k = 0; k < HH; k++) {
                    float xk = xv[k], hk = hv[k];
                    gir += xk*w0[k]; giz += xk*w1[k]; gin += xk*w2[k];
                    ghr += hk*v0[k]; ghz += hk*v1[k]; ghn += hk*v2[k];
                }
                float r  = sigmoidf_(gir + ghr);
                float z  = sigmoidf_(giz + ghz);
                float nn = tanhf(gin + r*ghn);
                nxt[n*HS+hd] = (1.f - z)*nn + z*hv[hd];
            }
        }
        __syncthreads();
    }

    // ---------- write output: h_aqi then h_meo, flattened ----------
    const float* hf = s.h[TT & 1];   // TT even -> final state in h[0]
    for (int p = tid; p < NN*HH; p += THREADS) {
        int n = p >> 5, hd = p & 31;
        float v = hf[n*HS+hd];
        if (n < NA) out[((size_t)b*NA + n)*HH + hd] = v;
        else        out[(size_t)NB*NA*HH + ((size_t)b*NM + (n-NA))*HH + hd] = v;
    }
}

extern "C" void kernel_launch(void* const* d_in, const int* in_sizes, int n_in,
                              void* d_out, int out_size)
{
    (void)in_sizes; (void)n_in; (void)out_size;
    cudaFuncSetAttribute(chgat_gru_kernel,
                         cudaFuncAttributeMaxDynamicSharedMemorySize,
                         (int)sizeof(SM));
    chgat_gru_kernel<<<NB, THREADS, sizeof(SM)>>>(
        (const float*)d_in[0],  (const float*)d_in[1],
        (const float*)d_in[2],  (const float*)d_in[3],
        (const float*)d_in[4],
        (const float*)d_in[5],  (const float*)d_in[6],
        (const float*)d_in[7],  (const float*)d_in[8],
        (const float*)d_in[9],  (const float*)d_in[10],
        (const float*)d_in[11], (const float*)d_in[12],
        (const float*)d_in[13],
        (const float*)d_in[14], (const float*)d_in[15],
        (const float*)d_in[16], (const float*)d_in[17],
        (const float*)d_in[18], (const float*)d_in[19],
        (const float*)d_in[20], (const float*)d_in[21],
        (const float*)d_in[22], (const float*)d_in[23],
        (const float*)d_in[24], (const float*)d_in[25],
        (const float*)d_in[26], (const float*)d_in[27],
        (const float*)d_in[28], (const float*)d_in[29],
        (const int*)d_in[30],   (const int*)d_in[31],
        (float*)d_out);
}

// round 4
// speedup vs baseline: 2.0994x; 2.0994x over previous
#include <cuda_runtime.h>

#define NB   1024
#define TT   48
#define NAq  35
#define NMe  18
#define NN   53
#define HH   32
#define CTXD 60
#define THREADS 256
#define W56  56     // transposed row width (node axis, padded; M segment starts at col 36)
#define HS   33     // padded stride for [node][hd] arrays

// node n (0..52) -> padded column index cn (A: 0..34, M: 36..53)
#define CN(n) ((n) < NAq ? (n) : (n) + 1)

struct __align__(16) SM {
    // float4-accessed arrays first (all widths multiple of 4)
    float baseT[NN*W56];     // [j][cn(i)] mask-folded adj_norm * a_last
    float attT[NN*W56];      // [j][cn(i)] logits -> exp values
    float h_T[HH*W56];       // [hd][cn(n)] GRU hidden state (single buffer)
    float gat_T[HH*W56];     // [hd][cn(n)] featf (p1/p2) then GAT output (p5/p6)
    float xT[6*W56];         // [k][cn(n)] raw features transposed
    float inv[W56];          // softmax 1/sum per column
    // scalar-accessed
    float wih_a[96*HS], whh_a[96*HS], wih_m[96*HS], whh_m[96*HS];
    float Wxa[6*HH], Wxm[4*HH], Wua[14*HH], Wum[14*HH];
    float a_src[4][HH], a_dst[4][HH], a_last[4];
    float bih_a[96], bhh_a[96], bih_m[96], bhh_m[96];
    float emb_aqi[158];      // id@0(35) month@35(13) weekday@48(7) hour@55(24), float2 rows
    float emb_meo[142];      // wind@0(9) id@9(18) month@27(13) weekday@40(7) hour@47(24)
    float attri[NN*HS];      // [node][hd] aggregation values
    float srcA[NN], srcM[NN], dstA[NN], dstM[NN];
    float ctxsA[NN], ctxsM[NN], ctxdA[NN], ctxdM[NN];
    int   exa[NAq*4];
    int   exm[NMe*5];
};

__device__ __forceinline__ float sigf(float x) {
    return __fdividef(1.f, 1.f + __expf(-x));
}
__device__ __forceinline__ float tanhf_fast(float x) {
    return 2.f * sigf(2.f * x) - 1.f;
}

// ---- phase 1: attri + featf for one 4-node group ----
__device__ __forceinline__ void feat_job(SM& s, int g, int lane) {
    const bool isA = g < 9;
    const int cn0 = isA ? 4*g : 36 + 4*(g-9);
    float av[4] = {0,0,0,0}, fv[4] = {0,0,0,0};
    if (isA) {
        #pragma unroll
        for (int k = 0; k < 6; k++) {
            float4 x4 = *(const float4*)(s.xT + k*W56 + cn0);
            float wa = s.Wxa[k*HH+lane], wu = s.Wua[k*HH+lane];
            av[0] += x4.x*wa; av[1] += x4.y*wa; av[2] += x4.z*wa; av[3] += x4.w*wa;
            fv[0] += x4.x*wu; fv[1] += x4.y*wu; fv[2] += x4.z*wu; fv[3] += x4.w*wu;
        }
        const int offs[4] = {0, 35, 48, 55};
        #pragma unroll
        for (int e = 0; e < 4; e++) {
            float wA = s.Wua[(6+2*e)*HH+lane], wB = s.Wua[(7+2*e)*HH+lane];
            #pragma unroll
            for (int i = 0; i < 4; i++) {
                int n = cn0 + i;
                int idx = (n < NAq) ? s.exa[n*4+e] : 0;
                float2 em = *(const float2*)(s.emb_aqi + (offs[e]+idx)*2);
                fv[i] += em.x*wA + em.y*wB;
            }
        }
        #pragma unroll
        for (int i = 0; i < 4; i++)
            if (cn0 + i < NAq) s.attri[(cn0+i)*HS+lane] = av[i];
    } else {
        #pragma unroll
        for (int k = 0; k < 4; k++) {
            float4 x4 = *(const float4*)(s.xT + k*W56 + cn0);
            float wa = s.Wxm[k*HH+lane], wu = s.Wum[k*HH+lane];
            av[0] += x4.x*wa; av[1] += x4.y*wa; av[2] += x4.z*wa; av[3] += x4.w*wa;
            fv[0] += x4.x*wu; fv[1] += x4.y*wu; fv[2] += x4.z*wu; fv[3] += x4.w*wu;
        }
        const int offs[5] = {0, 9, 27, 40, 47};
        #pragma unroll
        for (int e = 0; e < 5; e++) {
            float wA = s.Wum[(4+2*e)*HH+lane], wB = s.Wum[(5+2*e)*HH+lane];
            #pragma unroll
            for (int i = 0; i < 4; i++) {
                int cn = cn0 + i;
                int idx = (cn <= 53) ? s.exm[(cn-36)*5+e] : 0;
                float2 em = *(const float2*)(s.emb_meo + (offs[e]+idx)*2);
                fv[i] += em.x*wA + em.y*wB;
            }
        }
        #pragma unroll
        for (int i = 0; i < 4; i++)
            if (cn0 + i <= 53) s.attri[(cn0+i-1)*HS+lane] = av[i];
    }
    *(float4*)(s.gat_T + lane*W56 + cn0) = make_float4(fv[0], fv[1], fv[2], fv[3]);
}

// ---- phase 5: GAT output for one 4-node group (att @ attri, scaled by inv) ----
__device__ __forceinline__ void gat_job(SM& s, int g, int lane) {
    const int cn0 = (g < 9) ? 4*g : 36 + 4*(g-9);
    float acc0=0.f, acc1=0.f, acc2=0.f, acc3=0.f;
    #pragma unroll 4
    for (int j = 0; j < NN; j++) {
        float av = s.attri[j*HS + lane];
        float4 a4 = *(const float4*)(s.attT + j*W56 + cn0);
        acc0 += a4.x*av; acc1 += a4.y*av; acc2 += a4.z*av; acc3 += a4.w*av;
    }
    float4 iv = *(const float4*)(s.inv + cn0);
    *(float4*)(s.gat_T + lane*W56 + cn0) =
        make_float4(acc0*iv.x, acc1*iv.y, acc2*iv.z, acc3*iv.w);
}

// ---- phase 6a: GRU for one 4-node group, returns new hidden (not yet stored) ----
__device__ __forceinline__ float4 gru_job(const SM& s, int g, int lane) {
    const bool isA = g < 9;
    const int cn0 = isA ? 4*g : 36 + 4*(g-9);
    const float* WI = isA ? s.wih_a : s.wih_m;
    const float* WH = isA ? s.whh_a : s.whh_m;
    const float* BI = isA ? s.bih_a : s.bih_m;
    const float* BH = isA ? s.bhh_a : s.bhh_m;
    const float* wi0 = WI + lane*HS;
    const float* wi1 = wi0 + 32*HS;
    const float* wi2 = wi0 + 64*HS;
    const float* vh0 = WH + lane*HS;
    const float* vh1 = vh0 + 32*HS;
    const float* vh2 = vh0 + 64*HS;

    float air[4]={0,0,0,0}, aiz[4]={0,0,0,0}, ain[4]={0,0,0,0};
    float ahr[4]={0,0,0,0}, ahz[4]={0,0,0,0}, ahn[4]={0,0,0,0};
    #pragma unroll 8
    for (int k = 0; k < HH; k++) {
        float4 x4 = *(const float4*)(s.gat_T + k*W56 + cn0);
        float4 h4 = *(const float4*)(s.h_T  + k*W56 + cn0);
        float a0 = wi0[k], a1 = wi1[k], a2 = wi2[k];
        float b0 = vh0[k], b1 = vh1[k], b2 = vh2[k];
        air[0] += x4.x*a0; air[1] += x4.y*a0; air[2] += x4.z*a0; air[3] += x4.w*a0;
        aiz[0] += x4.x*a1; aiz[1] += x4.y*a1; aiz[2] += x4.z*a1; aiz[3] += x4.w*a1;
        ain[0] += x4.x*a2; ain[1] += x4.y*a2; ain[2] += x4.z*a2; ain[3] += x4.w*a2;
        ahr[0] += h4.x*b0; ahr[1] += h4.y*b0; ahr[2] += h4.z*b0; ahr[3] += h4.w*b0;
        ahz[0] += h4.x*b1; ahz[1] += h4.y*b1; ahz[2] += h4.z*b1; ahz[3] += h4.w*b1;
        ahn[0] += h4.x*b2; ahn[1] += h4.y*b2; ahn[2] += h4.z*b2; ahn[3] += h4.w*b2;
    }
    float b_ir = BI[lane], b_iz = BI[32+lane], b_in = BI[64+lane];
    float b_hr = BH[lane], b_hz = BH[32+lane], b_hn = BH[64+lane];
    float4 hv = *(const float4*)(s.h_T + lane*W56 + cn0);
    float hvv[4] = {hv.x, hv.y, hv.z, hv.w};
    float o[4];
    #pragma unroll
    for (int i = 0; i < 4; i++) {
        float r  = sigf(air[i] + b_ir + ahr[i] + b_hr);
        float z  = sigf(aiz[i] + b_iz + ahz[i] + b_hz);
        float nn = tanhf_fast(ain[i] + b_in + r*(ahn[i] + b_hn));
        o[i] = (1.f - z)*nn + z*hvv[i];
    }
    return make_float4(o[0], o[1], o[2], o[3]);
}

__global__ __launch_bounds__(THREADS, 2)
void chgat_gru_kernel(
    const float* __restrict__ X_aqi, const float* __restrict__ X_meo,
    const float* __restrict__ ctx,   const float* __restrict__ adj,
    const float* __restrict__ adjn,
    const float* __restrict__ e_ai,  const float* __restrict__ e_amo,
    const float* __restrict__ e_awd, const float* __restrict__ e_ahr,
    const float* __restrict__ e_mw,  const float* __restrict__ e_mi,
    const float* __restrict__ e_mmo, const float* __restrict__ e_mwd,
    const float* __restrict__ e_mhr,
    const float* __restrict__ Wxa,   const float* __restrict__ Wxm,
    const float* __restrict__ Wua,   const float* __restrict__ Wum,
    const float* __restrict__ a_aa,  const float* __restrict__ a_am,
    const float* __restrict__ a_ma,  const float* __restrict__ a_mm,
    const float* __restrict__ gaw_ih, const float* __restrict__ gaw_hh,
    const float* __restrict__ gab_ih, const float* __restrict__ gab_hh,
    const float* __restrict__ gmw_ih, const float* __restrict__ gmw_hh,
    const float* __restrict__ gmb_ih, const float* __restrict__ gmb_hh,
    const int* __restrict__ Xa_ex,   const int* __restrict__ Xm_ex,
    float* __restrict__ out)
{
    extern __shared__ char smraw[];
    SM& s = *reinterpret_cast<SM*>(smraw);

    const int tid  = threadIdx.x;
    const int b    = blockIdx.x;
    const int lane = tid & 31;
    const int wid  = tid >> 5;

    // ---------- one-time setup ----------
    for (int i = tid; i < 6*HH;  i += THREADS) s.Wxa[i] = Wxa[i];
    for (int i = tid; i < 4*HH;  i += THREADS) s.Wxm[i] = Wxm[i];
    for (int i = tid; i < 14*HH; i += THREADS) { s.Wua[i] = Wua[i]; s.Wum[i] = Wum[i]; }
    for (int i = tid; i < 96*HH; i += THREADS) {
        int g = i >> 5, k = i & 31;
        s.wih_a[g*HS+k] = gaw_ih[i]; s.whh_a[g*HS+k] = gaw_hh[i];
        s.wih_m[g*HS+k] = gmw_ih[i]; s.whh_m[g*HS+k] = gmw_hh[i];
    }
    for (int i = tid; i < 96; i += THREADS) {
        s.bih_a[i] = gab_ih[i]; s.bhh_a[i] = gab_hh[i];
        s.bih_m[i] = gmb_ih[i]; s.bhh_m[i] = gmb_hh[i];
    }
    for (int i = tid; i < 4*HH; i += THREADS) {
        int c = i >> 5, k = i & 31;
        const float* a = (c==0)?a_aa:(c==1)?a_am:(c==2)?a_ma:a_mm;
        s.a_src[c][k] = a[k];
        s.a_dst[c][k] = a[92+k];
    }
    if (tid < 4) {
        const float* a = (tid==0)?a_aa:(tid==1)?a_am:(tid==2)?a_ma:a_mm;
        s.a_last[tid] = a[184];
    }
    for (int i = tid; i < 70; i += THREADS) s.emb_aqi[i]      = e_ai[i];
    for (int i = tid; i < 26; i += THREADS) s.emb_aqi[70+i]   = e_amo[i];
    for (int i = tid; i < 14; i += THREADS) s.emb_aqi[96+i]   = e_awd[i];
    for (int i = tid; i < 48; i += THREADS) s.emb_aqi[110+i]  = e_ahr[i];
    for (int i = tid; i < 18; i += THREADS) s.emb_meo[i]      = e_mw[i];
    for (int i = tid; i < 36; i += THREADS) s.emb_meo[18+i]   = e_mi[i];
    for (int i = tid; i < 26; i += THREADS) s.emb_meo[54+i]   = e_mmo[i];
    for (int i = tid; i < 14; i += THREADS) s.emb_meo[80+i]   = e_mwd[i];
    for (int i = tid; i < 48; i += THREADS) s.emb_meo[94+i]   = e_mhr[i];
    for (int i = tid; i < HH*W56; i += THREADS) s.h_T[i] = 0.f;
    __syncthreads();

    // context dots (role x node), once
    for (int p = tid; p < 4*NN; p += THREADS) {
        int n = p % NN, role = p / NN;
        int c;
        if (role == 0)      c = (n<NAq)?0:2;
        else if (role == 1) c = (n<NAq)?1:3;
        else if (role == 2) c = (n<NAq)?0:1;
        else                c = (n<NAq)?2:3;
        const float* a = (c==0)?a_aa:(c==1)?a_am:(c==2)?a_ma:a_mm;
        const float* w = (role < 2) ? (a + 32) : (a + 124);
        float acc = 0.f;
        #pragma unroll 4
        for (int k = 0; k < CTXD; k++) acc += ctx[n*CTXD+k]*w[k];
        if (role == 0)      s.ctxsA[n] = acc;
        else if (role == 1) s.ctxsM[n] = acc;
        else if (role == 2) s.ctxdA[n] = acc;
        else                s.ctxdM[n] = acc;
    }
    __syncthreads();
    // baseT (needs a_last in smem)
    for (int p = tid; p < NN*NN; p += THREADS) {
        int j = p / NN, i = p % NN;
        int c = ((i < NAq) ? 0 : 2) + ((j < NAq) ? 0 : 1);
        float v = (adj[i*NN+j] > 0.f) ? adjn[i*NN+j]*s.a_last[c] : -1e30f;
        s.baseT[j*W56 + CN(i)] = v;
    }
    __syncthreads();

    // ---------- timestep loop ----------
    for (int t = 0; t < TT; t++) {
        // p0: load + transpose raw features
        {
            const float* gx = X_aqi + (size_t)(b*TT + t)*NAq*6;
            for (int i = tid; i < NAq*6; i += THREADS) {
                int n = i/6, k = i%6;
                s.xT[k*W56 + n] = gx[i];
            }
            const float* gm = X_meo + (size_t)(b*TT + t)*NMe*4;
            for (int i = tid; i < NMe*4; i += THREADS) {
                int m = i/4, k = i%4;
                s.xT[k*W56 + 36 + m] = gm[i];
            }
            const int* ga = Xa_ex + (size_t)(b*TT + t)*NAq*4;
            for (int i = tid; i < NAq*4; i += THREADS) s.exa[i] = ga[i];
            const int* gme = Xm_ex + (size_t)(b*TT + t)*NMe*5;
            for (int i = tid; i < NMe*5; i += THREADS) s.exm[i] = gme[i];
        }
        __syncthreads();

        // p1: attri + featf (14 groups over 8 warps)
        for (int g = wid; g < 14; g += 8) feat_job(s, g, lane);
        __syncthreads();

        // p2: src/dst projections
        {
            int role = tid >> 6, q = tid & 63;
            bool valid = q < NN;
            int cn = valid ? CN(q) : 0;
            int c; float acc; const float* w;
            if (role == 0)      { c = (q<NAq)?0:2; w = s.a_src[c]; acc = valid ? s.ctxsA[q] : 0.f; }
            else if (role == 1) { c = (q<NAq)?1:3; w = s.a_src[c]; acc = valid ? s.ctxsM[q] : 0.f; }
            else if (role == 2) { c = (q<NAq)?0:1; w = s.a_dst[c]; acc = valid ? s.ctxdA[q] : 0.f; }
            else                { c = (q<NAq)?2:3; w = s.a_dst[c]; acc = valid ? s.ctxdM[q] : 0.f; }
            #pragma unroll 8
            for (int k = 0; k < HH; k++) acc += s.gat_T[k*W56 + cn] * w[k];
            if (valid) {
                if (role == 0)      s.srcA[q] = acc;
                else if (role == 1) s.srcM[q] = acc;
                else if (role == 2) s.dstA[q] = acc;
                else                s.dstM[q] = acc;
            }
        }
        __syncthreads();

        // p3+p4: logits + softmax, thread per column
        if (tid < W56) {
            int cn = tid;
            bool valid = (cn != 35) && (cn <= 53);
            if (valid) {
                int i = (cn < 35) ? cn : cn - 1;
                float sA = s.srcA[i], sM = s.srcM[i];
                const float* dp = (i < NAq) ? s.dstA : s.dstM;
                float m = -3.0e38f;
                for (int j = 0; j < NN; j++) {
                    float x = ((j < NAq) ? sA : sM) + dp[j] + s.baseT[j*W56+cn];
                    x = (x >= 0.f) ? x : 0.2f*x;
                    s.attT[j*W56+cn] = x;
                    m = fmaxf(m, x);
                }
                float sum = 0.f;
                for (int j = 0; j < NN; j++) {
                    float v = __expf(s.attT[j*W56+cn] - m);
                    s.attT[j*W56+cn] = v;
                    sum += v;
                }
                s.inv[cn] = __fdividef(1.f, sum);
            } else {
                s.inv[cn] = 0.f;
            }
        }
        __syncthreads();

        // p5: GAT output
        for (int g = wid; g < 14; g += 8) gat_job(s, g, lane);
        __syncthreads();

        // p6: GRU (accumulate in regs, barrier, then store in place)
        {
            int g0 = wid, g1 = wid + 8;
            float4 nh0 = gru_job(s, g0, lane);
            float4 nh1;
            if (g1 < 14) nh1 = gru_job(s, g1, lane);
            __syncthreads();
            {
                int cn0 = (g0 < 9) ? 4*g0 : 36 + 4*(g0-9);
                *(float4*)(s.h_T + lane*W56 + cn0) = nh0;
            }
            if (g1 < 14) {
                int cn1 = (g1 < 9) ? 4*g1 : 36 + 4*(g1-9);
                *(float4*)(s.h_T + lane*W56 + cn1) = nh1;
            }
        }
        __syncthreads();
    }

    // ---------- output ----------
    for (int p = tid; p < NN*HH; p += THREADS) {
        int n = p >> 5, hd = p & 31;
        float v = s.h_T[hd*W56 + CN(n)];
        if (n < NAq) out[((size_t)b*NAq + n)*HH + hd] = v;
        else         out[(size_t)NB*NAq*HH + ((size_t)b*NMe + (n-NAq))*HH + hd] = v;
    }
}

extern "C" void kernel_launch(void* const* d_in, const int* in_sizes, int n_in,
                              void* d_out, int out_size)
{
    (void)in_sizes; (void)n_in; (void)out_size;
    cudaFuncSetAttribute(chgat_gru_kernel,
                         cudaFuncAttributeMaxDynamicSharedMemorySize,
                         (int)sizeof(SM));
    chgat_gru_kernel<<<NB, THREADS, sizeof(SM)>>>(
        (const float*)d_in[0],  (const float*)d_in[1],
        (const float*)d_in[2],  (const float*)d_in[3],
        (const float*)d_in[4],
        (const float*)d_in[5],  (const float*)d_in[6],
        (const float*)d_in[7],  (const float*)d_in[8],
        (const float*)d_in[9],  (const float*)d_in[10],
        (const float*)d_in[11], (const float*)d_in[12],
        (const float*)d_in[13],
        (const float*)d_in[14], (const float*)d_in[15],
        (const float*)d_in[16], (const float*)d_in[17],
        (const float*)d_in[18], (const float*)d_in[19],
        (const float*)d_in[20], (const float*)d_in[21],
        (const float*)d_in[22], (const float*)d_in[23],
        (const float*)d_in[24], (const float*)d_in[25],
        (const float*)d_in[26], (const float*)d_in[27],
        (const float*)d_in[28], (const float*)d_in[29],
        (const int*)d_in[30],   (const int*)d_in[31],
        (float*)d_out);
}

// round 5
// speedup vs baseline: 2.1028x; 1.0016x over previous
#include <cuda_runtime.h>

#define NB   1024
#define TT   48
#define NAq  35
#define NMe  18
#define NN   53
#define HH   32
#define CTXD 60
#define THREADS 256
#define WD   64     // node-column width for h_T/gat_T/xT (A:0-34 pad 35-39, M:40-57 pad 58-63)
#define SW   60     // row stride for baseT/attT (conflict-free for quad softmax, 16B aligned)

#define CN(n) ((n) < NAq ? (n) : (n) + 5)

typedef unsigned long long u64;

struct __align__(16) SM {
    float baseT[NN*SW];
    float attT[NN*SW + 8];      // +8 tail pad: tile-7 float4 overflow at j=52
    float h_T[HH*WD];           // [hd][cn]
    float gat_T[HH*WD];         // [hd][cn] featf then GAT output
    float xT[6*WD];             // [k][cn]
    float inv[WD];
    float wihT_a[HH*96], whhT_a[HH*96], wihT_m[HH*96], whhT_m[HH*96]; // [k][gate]
    float Wxa[6*HH], Wxm[4*HH], Wua[14*HH], Wum[14*HH];
    float a_src[4][HH], a_dst[4][HH], a_last[4];
    float bih_a[96], bhh_a[96], bih_m[96], bhh_m[96];
    float emb_aqi[158];
    float emb_meo[142];
    float attri[NN*HH];         // [node][hd]
    float srcA[NN], srcM[NN], dstA[NN], dstM[NN];
    float ctxsA[NN], ctxsM[NN], ctxdA[NN], ctxdM[NN];
    int   exa[NAq*4];
    int   exm[NMe*5];
};

__device__ __forceinline__ u64 pk2(float lo, float hi) {
    u64 r; asm("mov.b64 %0,{%1,%2};" : "=l"(r) : "f"(lo), "f"(hi)); return r;
}
__device__ __forceinline__ u64 dup2(float v) { return pk2(v, v); }
__device__ __forceinline__ float2 up2(u64 a) {
    float2 r; asm("mov.b64 {%0,%1},%2;" : "=f"(r.x), "=f"(r.y) : "l"(a)); return r;
}
__device__ __forceinline__ void fma2(u64& d, u64 a, u64 b) {
    asm("fma.rn.f32x2 %0,%1,%2,%0;" : "+l"(d) : "l"(a), "l"(b));
}
__device__ __forceinline__ u64 mul2(u64 a, u64 b) {
    u64 r; asm("mul.rn.f32x2 %0,%1,%2;" : "=l"(r) : "l"(a), "l"(b)); return r;
}
__device__ __forceinline__ float sigf(float x) {
    return __fdividef(1.f, 1.f + __expf(-x));
}
__device__ __forceinline__ float tanhf_fast(float x) {
    return 2.f * sigf(2.f * x) - 1.f;
}

__global__ __launch_bounds__(THREADS, 2)
void chgat_gru_kernel(
    const float* __restrict__ X_aqi, const float* __restrict__ X_meo,
    const float* __restrict__ ctx,   const float* __restrict__ adj,
    const float* __restrict__ adjn,
    const float* __restrict__ e_ai,  const float* __restrict__ e_amo,
    const float* __restrict__ e_awd, const float* __restrict__ e_ahr,
    const float* __restrict__ e_mw,  const float* __restrict__ e_mi,
    const float* __restrict__ e_mmo, const float* __restrict__ e_mwd,
    const float* __restrict__ e_mhr,
    const float* __restrict__ Wxa,   const float* __restrict__ Wxm,
    const float* __restrict__ Wua,   const float* __restrict__ Wum,
    const float* __restrict__ a_aa,  const float* __restrict__ a_am,
    const float* __restrict__ a_ma,  const float* __restrict__ a_mm,
    const float* __restrict__ gaw_ih, const float* __restrict__ gaw_hh,
    const float* __restrict__ gab_ih, const float* __restrict__ gab_hh,
    const float* __restrict__ gmw_ih, const float* __restrict__ gmw_hh,
    const float* __restrict__ gmb_ih, const float* __restrict__ gmb_hh,
    const int* __restrict__ Xa_ex,   const int* __restrict__ Xm_ex,
    float* __restrict__ out)
{
    extern __shared__ char smraw[];
    SM& s = *reinterpret_cast<SM*>(smraw);

    const int tid  = threadIdx.x;
    const int b    = blockIdx.x;
    const int lane = tid & 31;
    const int wid  = tid >> 5;

    // ---------- one-time setup ----------
    for (int i = tid; i < 6*HH;  i += THREADS) s.Wxa[i] = Wxa[i];
    for (int i = tid; i < 4*HH;  i += THREADS) s.Wxm[i] = Wxm[i];
    for (int i = tid; i < 14*HH; i += THREADS) { s.Wua[i] = Wua[i]; s.Wum[i] = Wum[i]; }
    // GRU weights transposed [k][gate]; dest-indexed (conflict-free stores)
    for (int i = tid; i < 96*HH; i += THREADS) {
        int k = i / 96, g = i % 96;
        s.wihT_a[i] = gaw_ih[g*HH+k]; s.whhT_a[i] = gaw_hh[g*HH+k];
        s.wihT_m[i] = gmw_ih[g*HH+k]; s.whhT_m[i] = gmw_hh[g*HH+k];
    }
    for (int i = tid; i < 96; i += THREADS) {
        s.bih_a[i] = gab_ih[i]; s.bhh_a[i] = gab_hh[i];
        s.bih_m[i] = gmb_ih[i]; s.bhh_m[i] = gmb_hh[i];
    }
    for (int i = tid; i < 4*HH; i += THREADS) {
        int c = i >> 5, k = i & 31;
        const float* a = (c==0)?a_aa:(c==1)?a_am:(c==2)?a_ma:a_mm;
        s.a_src[c][k] = a[k];
        s.a_dst[c][k] = a[92+k];
    }
    if (tid < 4) {
        const float* a = (tid==0)?a_aa:(tid==1)?a_am:(tid==2)?a_ma:a_mm;
        s.a_last[tid] = a[184];
    }
    for (int i = tid; i < 70; i += THREADS) s.emb_aqi[i]      = e_ai[i];
    for (int i = tid; i < 26; i += THREADS) s.emb_aqi[70+i]   = e_amo[i];
    for (int i = tid; i < 14; i += THREADS) s.emb_aqi[96+i]   = e_awd[i];
    for (int i = tid; i < 48; i += THREADS) s.emb_aqi[110+i]  = e_ahr[i];
    for (int i = tid; i < 18; i += THREADS) s.emb_meo[i]      = e_mw[i];
    for (int i = tid; i < 36; i += THREADS) s.emb_meo[18+i]   = e_mi[i];
    for (int i = tid; i < 26; i += THREADS) s.emb_meo[54+i]   = e_mmo[i];
    for (int i = tid; i < 14; i += THREADS) s.emb_meo[80+i]   = e_mwd[i];
    for (int i = tid; i < 48; i += THREADS) s.emb_meo[94+i]   = e_mhr[i];
    for (int i = tid; i < HH*WD; i += THREADS) s.h_T[i] = 0.f;
    for (int i = tid; i < 6*WD; i += THREADS) s.xT[i] = 0.f;
    if (tid < 8) s.attT[NN*SW + tid] = 0.f;
    __syncthreads();

    // context dots (role x node), once
    for (int p = tid; p < 4*NN; p += THREADS) {
        int n = p % NN, role = p / NN;
        int c;
        if (role == 0)      c = (n<NAq)?0:2;
        else if (role == 1) c = (n<NAq)?1:3;
        else if (role == 2) c = (n<NAq)?0:1;
        else                c = (n<NAq)?2:3;
        const float* a = (c==0)?a_aa:(c==1)?a_am:(c==2)?a_ma:a_mm;
        const float* w = (role < 2) ? (a + 32) : (a + 124);
        float acc = 0.f;
        #pragma unroll 4
        for (int k = 0; k < CTXD; k++) acc += ctx[n*CTXD+k]*w[k];
        if (role == 0)      s.ctxsA[n] = acc;
        else if (role == 1) s.ctxsM[n] = acc;
        else if (role == 2) s.ctxdA[n] = acc;
        else                s.ctxdM[n] = acc;
    }
    __syncthreads();
    for (int p = tid; p < NN*NN; p += THREADS) {
        int j = p / NN, i = p % NN;
        int c = ((i < NAq) ? 0 : 2) + ((j < NAq) ? 0 : 1);
        float v = (adj[i*NN+j] > 0.f) ? adjn[i*NN+j]*s.a_last[c] : -1e30f;
        s.baseT[j*SW + CN(i)] = v;
    }
    __syncthreads();

    const int  cn0 = wid * 8;          // this warp's 8-column tile
    const bool isA = (wid < 5);
    const float* WI = isA ? s.wihT_a : s.wihT_m;
    const float* WH = isA ? s.whhT_a : s.whhT_m;
    const float* BI = isA ? s.bih_a  : s.bih_m;
    const float* BH = isA ? s.bhh_a  : s.bhh_m;
    const float b_ir = BI[lane], b_iz = BI[32+lane], b_in = BI[64+lane];
    const float b_hr = BH[lane], b_hz = BH[32+lane], b_hn = BH[64+lane];

    // ---------- timestep loop ----------
    for (int t = 0; t < TT; t++) {
        // p0: load + transpose raw features
        {
            const float* gx = X_aqi + (size_t)(b*TT + t)*NAq*6;
            for (int i = tid; i < NAq*6; i += THREADS) {
                int n = i/6, k = i%6;
                s.xT[k*WD + n] = gx[i];
            }
            const float* gm = X_meo + (size_t)(b*TT + t)*NMe*4;
            for (int i = tid; i < NMe*4; i += THREADS) {
                int m = i/4, k = i%4;
                s.xT[k*WD + 40 + m] = gm[i];
            }
            const int* ga = Xa_ex + (size_t)(b*TT + t)*NAq*4;
            for (int i = tid; i < NAq*4; i += THREADS) s.exa[i] = ga[i];
            const int* gme = Xm_ex + (size_t)(b*TT + t)*NMe*5;
            for (int i = tid; i < NMe*5; i += THREADS) s.exm[i] = gme[i];
        }
        __syncthreads();

        // p1: attri + featf, one 8-node tile per warp, f32x2 packed
        {
            u64 av[4] = {0,0,0,0}, fv[4] = {0,0,0,0};
            if (isA) {
                #pragma unroll
                for (int k = 0; k < 6; k++) {
                    ulonglong2 xa = *(const ulonglong2*)(s.xT + k*WD + cn0);
                    ulonglong2 xb = *(const ulonglong2*)(s.xT + k*WD + cn0 + 4);
                    u64 wa = dup2(s.Wxa[k*HH+lane]);
                    u64 wu = dup2(s.Wua[k*HH+lane]);
                    fma2(av[0], xa.x, wa); fma2(av[1], xa.y, wa);
                    fma2(av[2], xb.x, wa); fma2(av[3], xb.y, wa);
                    fma2(fv[0], xa.x, wu); fma2(fv[1], xa.y, wu);
                    fma2(fv[2], xb.x, wu); fma2(fv[3], xb.y, wu);
                }
                const int offs[4] = {0, 35, 48, 55};
                #pragma unroll
                for (int e = 0; e < 4; e++) {
                    u64 wA = dup2(s.Wua[(6+2*e)*HH+lane]);
                    u64 wB = dup2(s.Wua[(7+2*e)*HH+lane]);
                    #pragma unroll
                    for (int pr = 0; pr < 4; pr++) {
                        int n0 = cn0 + 2*pr, n1 = n0 + 1;
                        int i0 = (n0 < NAq) ? s.exa[n0*4+e] : 0;
                        int i1 = (n1 < NAq) ? s.exa[n1*4+e] : 0;
                        float2 em0 = *(const float2*)(s.emb_aqi + (offs[e]+i0)*2);
                        float2 em1 = *(const float2*)(s.emb_aqi + (offs[e]+i1)*2);
                        fma2(fv[pr], pk2(em0.x, em1.x), wA);
                        fma2(fv[pr], pk2(em0.y, em1.y), wB);
                    }
                }
                #pragma unroll
                for (int pr = 0; pr < 4; pr++) {
                    float2 a2 = up2(av[pr]);
                    int n0 = cn0 + 2*pr;
                    if (n0   < NAq) s.attri[n0*HH + lane]     = a2.x;
                    if (n0+1 < NAq) s.attri[(n0+1)*HH + lane] = a2.y;
                }
            } else {
                #pragma unroll
                for (int k = 0; k < 4; k++) {
                    ulonglong2 xa = *(const ulonglong2*)(s.xT + k*WD + cn0);
                    ulonglong2 xb = *(const ulonglong2*)(s.xT + k*WD + cn0 + 4);
                    u64 wa = dup2(s.Wxm[k*HH+lane]);
                    u64 wu = dup2(s.Wum[k*HH+lane]);
                    fma2(av[0], xa.x, wa); fma2(av[1], xa.y, wa);
                    fma2(av[2], xb.x, wa); fma2(av[3], xb.y, wa);
                    fma2(fv[0], xa.x, wu); fma2(fv[1], xa.y, wu);
                    fma2(fv[2], xb.x, wu); fma2(fv[3], xb.y, wu);
                }
                const int offs[5] = {0, 9, 27, 40, 47};
                #pragma unroll
                for (int e = 0; e < 5; e++) {
                    u64 wA = dup2(s.Wum[(4+2*e)*HH+lane]);
                    u64 wB = dup2(s.Wum[(5+2*e)*HH+lane]);
                    #pragma unroll
                    for (int pr = 0; pr < 4; pr++) {
                        int c0 = cn0 + 2*pr, c1 = c0 + 1;
                        int i0 = (c0 <= 57) ? s.exm[(c0-40)*5+e] : 0;
                        int i1 = (c1 <= 57) ? s.exm[(c1-40)*5+e] : 0;
                        float2 em0 = *(const float2*)(s.emb_meo + (offs[e]+i0)*2);
                        float2 em1 = *(const float2*)(s.emb_meo + (offs[e]+i1)*2);
                        fma2(fv[pr], pk2(em0.x, em1.x), wA);
                        fma2(fv[pr], pk2(em0.y, em1.y), wB);
                    }
                }
                #pragma unroll
                for (int pr = 0; pr < 4; pr++) {
                    float2 a2 = up2(av[pr]);
                    int c0 = cn0 + 2*pr;
                    if (c0   <= 57) s.attri[(c0-5)*HH + lane] = a2.x;
                    if (c0+1 <= 57) s.attri[(c0-4)*HH + lane] = a2.y;
                }
            }
            *(ulonglong2*)(s.gat_T + lane*WD + cn0)     = make_ulonglong2(fv[0], fv[1]);
            *(ulonglong2*)(s.gat_T + lane*WD + cn0 + 4) = make_ulonglong2(fv[2], fv[3]);
        }
        __syncthreads();

        // p2: src/dst projections (role x column)
        {
            int role = tid >> 6, q = tid & 63;
            bool valid = (q < NAq) || (q >= 40 && q < 58);
            int n = (q < NAq) ? q : q - 5;
            int c; float acc; const float* w;
            bool nA = q < NAq;
            if (role == 0)      { c = nA?0:2; w = s.a_src[c]; acc = valid ? s.ctxsA[n] : 0.f; }
            else if (role == 1) { c = nA?1:3; w = s.a_src[c]; acc = valid ? s.ctxsM[n] : 0.f; }
            else if (role == 2) { c = nA?0:1; w = s.a_dst[c]; acc = valid ? s.ctxdA[n] : 0.f; }
            else                { c = nA?2:3; w = s.a_dst[c]; acc = valid ? s.ctxdM[n] : 0.f; }
            #pragma unroll 8
            for (int k = 0; k < HH; k++) acc += s.gat_T[k*WD + q] * w[k];
            if (valid) {
                if (role == 0)      s.srcA[n] = acc;
                else if (role == 1) s.srcM[n] = acc;
                else if (role == 2) s.dstA[n] = acc;
                else                s.dstM[n] = acc;
            }
        }
        __syncthreads();

        // p3/4: logits + exp + sum, quad of threads per column (max-free, clamped)
        {
            int cn = tid >> 2, sub = tid & 3;
            bool valid = (cn < NAq) || (cn >= 40 && cn < 58);
            float sum = 0.f;
            if (valid) {
                int i = (cn < NAq) ? cn : cn - 5;
                float sAv = s.srcA[i], sMv = s.srcM[i];
                const float* dp = (i < NAq) ? s.dstA : s.dstM;
                for (int j = sub; j < NN; j += 4) {
                    float x = ((j < NAq) ? sAv : sMv) + dp[j] + s.baseT[j*SW+cn];
                    x = (x >= 0.f) ? x : 0.2f*x;
                    float v = __expf(fminf(x, 60.f));
                    s.attT[j*SW+cn] = v;
                    sum += v;
                }
            } else if (cn < SW) {
                for (int j = sub; j < NN; j += 4) s.attT[j*SW+cn] = 0.f;
            }
            sum += __shfl_xor_sync(0xffffffffu, sum, 1);
            sum += __shfl_xor_sync(0xffffffffu, sum, 2);
            if (sub == 0) s.inv[cn] = valid ? __fdividef(1.f, sum) : 0.f;
        }
        __syncthreads();

        // p5: GAT output (att @ attri, f32x2), same-warp tile — then fused GRU
        {
            u64 acc[4] = {0,0,0,0};
            #pragma unroll 4
            for (int j = 0; j < NN; j++) {
                u64 ap = dup2(s.attri[j*HH + lane]);
                ulonglong2 t0 = *(const ulonglong2*)(s.attT + j*SW + cn0);
                ulonglong2 t1 = *(const ulonglong2*)(s.attT + j*SW + cn0 + 4);
                fma2(acc[0], t0.x, ap); fma2(acc[1], t0.y, ap);
                fma2(acc[2], t1.x, ap); fma2(acc[3], t1.y, ap);
            }
            float4 iv0 = *(const float4*)(s.inv + cn0);
            float4 iv1 = *(const float4*)(s.inv + cn0 + 4);
            acc[0] = mul2(acc[0], pk2(iv0.x, iv0.y));
            acc[1] = mul2(acc[1], pk2(iv0.z, iv0.w));
            acc[2] = mul2(acc[2], pk2(iv1.x, iv1.y));
            acc[3] = mul2(acc[3], pk2(iv1.z, iv1.w));
            *(ulonglong2*)(s.gat_T + lane*WD + cn0)     = make_ulonglong2(acc[0], acc[1]);
            *(ulonglong2*)(s.gat_T + lane*WD + cn0 + 4) = make_ulonglong2(acc[2], acc[3]);
        }
        __syncwarp();

        // p6: GRU, same tile, f32x2 packed
        {
            u64 gr[4]={0,0,0,0}, gz[4]={0,0,0,0}, gn[4]={0,0,0,0};
            u64 hr[4]={0,0,0,0}, hz[4]={0,0,0,0}, hn[4]={0,0,0,0};
            #pragma unroll 4
            for (int k = 0; k < HH; k++) {
                ulonglong2 x0 = *(const ulonglong2*)(s.gat_T + k*WD + cn0);
                ulonglong2 x1 = *(const ulonglong2*)(s.gat_T + k*WD + cn0 + 4);
                ulonglong2 h0 = *(const ulonglong2*)(s.h_T  + k*WD + cn0);
                ulonglong2 h1 = *(const ulonglong2*)(s.h_T  + k*WD + cn0 + 4);
                u64 w0 = dup2(WI[k*96 + lane]);
                u64 w1 = dup2(WI[k*96 + 32 + lane]);
                u64 w2 = dup2(WI[k*96 + 64 + lane]);
                u64 v0 = dup2(WH[k*96 + lane]);
                u64 v1 = dup2(WH[k*96 + 32 + lane]);
                u64 v2 = dup2(WH[k*96 + 64 + lane]);
                fma2(gr[0], x0.x, w0); fma2(gr[1], x0.y, w0);
                fma2(gr[2], x1.x, w0); fma2(gr[3], x1.y, w0);
                fma2(gz[0], x0.x, w1); fma2(gz[1], x0.y, w1);
                fma2(gz[2], x1.x, w1); fma2(gz[3], x1.y, w1);
                fma2(gn[0], x0.x, w2); fma2(gn[1], x0.y, w2);
                fma2(gn[2], x1.x, w2); fma2(gn[3], x1.y, w2);
                fma2(hr[0], h0.x, v0); fma2(hr[1], h0.y, v0);
                fma2(hr[2], h1.x, v0); fma2(hr[3], h1.y, v0);
                fma2(hz[0], h0.x, v1); fma2(hz[1], h0.y, v1);
                fma2(hz[2], h1.x, v1); fma2(hz[3], h1.y, v1);
                fma2(hn[0], h0.x, v2); fma2(hn[1], h0.y, v2);
                fma2(hn[2], h1.x, v2); fma2(hn[3], h1.y, v2);
            }
            ulonglong2 ho0 = *(const ulonglong2*)(s.h_T + lane*WD + cn0);
            ulonglong2 ho1 = *(const ulonglong2*)(s.h_T + lane*WD + cn0 + 4);
            u64 hop[4] = {ho0.x, ho0.y, ho1.x, ho1.y};
            u64 res[4];
            #pragma unroll
            for (int p = 0; p < 4; p++) {
                float2 R = up2(gr[p]), Z = up2(gz[p]), Nn = up2(gn[p]);
                float2 HR = up2(hr[p]), HZ = up2(hz[p]), HN = up2(hn[p]);
                float2 HO = up2(hop[p]);
                float r0 = sigf(R.x + b_ir + HR.x + b_hr);
                float z0 = sigf(Z.x + b_iz + HZ.x + b_hz);
                float n0 = tanhf_fast(Nn.x + b_in + r0*(HN.x + b_hn));
                float o0 = (1.f - z0)*n0 + z0*HO.x;
                float r1 = sigf(R.y + b_ir + HR.y + b_hr);
                float z1 = sigf(Z.y + b_iz + HZ.y + b_hz);
                float n1 = tanhf_fast(Nn.y + b_in + r1*(HN.y + b_hn));
                float o1 = (1.f - z1)*n1 + z1*HO.y;
                res[p] = pk2(o0, o1);
            }
            __syncwarp();
            *(ulonglong2*)(s.h_T + lane*WD + cn0)     = make_ulonglong2(res[0], res[1]);
            *(ulonglong2*)(s.h_T + lane*WD + cn0 + 4) = make_ulonglong2(res[2], res[3]);
        }
        __syncthreads();
    }

    // ---------- output ----------
    for (int p = tid; p < NN*HH; p += THREADS) {
        int n = p >> 5, hd = p & 31;
        float v = s.h_T[hd*WD + CN(n)];
        if (n < NAq) out[((size_t)b*NAq + n)*HH + hd] = v;
        else         out[(size_t)NB*NAq*HH + ((size_t)b*NMe + (n-NAq))*HH + hd] = v;
    }
}

extern "C" void kernel_launch(void* const* d_in, const int* in_sizes, int n_in,
                              void* d_out, int out_size)
{
    (void)in_sizes; (void)n_in; (void)out_size;
    cudaFuncSetAttribute(chgat_gru_kernel,
                         cudaFuncAttributeMaxDynamicSharedMemorySize,
                         (int)sizeof(SM));
    chgat_gru_kernel<<<NB, THREADS, sizeof(SM)>>>(
        (const float*)d_in[0],  (const float*)d_in[1],
        (const float*)d_in[2],  (const float*)d_in[3],
        (const float*)d_in[4],
        (const float*)d_in[5],  (const float*)d_in[6],
        (const float*)d_in[7],  (const float*)d_in[8],
        (const float*)d_in[9],  (const float*)d_in[10],
        (const float*)d_in[11], (const float*)d_in[12],
        (const float*)d_in[13],
        (const float*)d_in[14], (const float*)d_in[15],
        (const float*)d_in[16], (const float*)d_in[17],
        (const float*)d_in[18], (const float*)d_in[19],
        (const float*)d_in[20], (const float*)d_in[21],
        (const float*)d_in[22], (const float*)d_in[23],
        (const float*)d_in[24], (const float*)d_in[25],
        (const float*)d_in[26], (const float*)d_in[27],
        (const float*)d_in[28], (const float*)d_in[29],
        (const int*)d_in[30],   (const int*)d_in[31],
        (float*)d_out);
}

// round 6
// speedup vs baseline: 2.2172x; 1.0544x over previous
#include <cuda_runtime.h>

#define NB   1024
#define TT   48
#define NAq  35
#define NMe  18
#define NN   53
#define HH   32
#define CTXD 60
#define THREADS 256
#define WD   64     // node-column width for h_T/gat_T/xT (A:0-34 pad 35-39, M:40-57 pad 58-63)
#define SW   60     // row stride for baseT/attT (conflict-free for quad softmax, 16B aligned)

#define CN(n) ((n) < NAq ? (n) : (n) + 5)

typedef unsigned long long u64;

struct __align__(16) SM {
    float baseT[NN*SW];
    float attT[NN*SW + 8];      // +8 tail pad: tile-7 float4 overflow at j=52
    float h_T[HH*WD];           // [hd][cn]
    float gat_T[HH*WD];         // [hd][cn] featf then GAT output
    float xT[6*WD];             // [k][cn]
    float inv[WD];
    float wihT_a[HH*96], whhT_a[HH*96], wihT_m[HH*96], whhT_m[HH*96]; // [k][gate]
    float Wxa[6*HH], Wxm[4*HH], Wua[14*HH], Wum[14*HH];
    float a_src[4][HH], a_dst[4][HH], a_last[4];
    float bih_a[96], bhh_a[96], bih_m[96], bhh_m[96];
    float emb_aqi[158];
    float emb_meo[142];
    float attri[NN*HH];         // [node][hd]
    float srcA[NN], srcM[NN], dstA[NN], dstM[NN];
    float ctxsA[NN], ctxsM[NN], ctxdA[NN], ctxdM[NN];
    int   exa[NAq*4];
    int   exm[NMe*5];
};

__device__ __forceinline__ u64 pk2(float lo, float hi) {
    u64 r; asm("mov.b64 %0,{%1,%2};" : "=l"(r) : "f"(lo), "f"(hi)); return r;
}
__device__ __forceinline__ u64 dup2(float v) { return pk2(v, v); }
__device__ __forceinline__ float2 up2(u64 a) {
    float2 r; asm("mov.b64 {%0,%1},%2;" : "=f"(r.x), "=f"(r.y) : "l"(a)); return r;
}
__device__ __forceinline__ void fma2(u64& d, u64 a, u64 b) {
    asm("fma.rn.f32x2 %0,%1,%2,%0;" : "+l"(d) : "l"(a), "l"(b));
}
__device__ __forceinline__ u64 mul2(u64 a, u64 b) {
    u64 r; asm("mul.rn.f32x2 %0,%1,%2;" : "=l"(r) : "l"(a), "l"(b)); return r;
}
__device__ __forceinline__ float sigf(float x) {
    return __fdividef(1.f, 1.f + __expf(-x));
}
__device__ __forceinline__ float tanhf_fast(float x) {
    return 2.f * sigf(2.f * x) - 1.f;
}

__global__ __launch_bounds__(THREADS, 2)
void chgat_gru_kernel(
    const float* __restrict__ X_aqi, const float* __restrict__ X_meo,
    const float* __restrict__ ctx,   const float* __restrict__ adj,
    const float* __restrict__ adjn,
    const float* __restrict__ e_ai,  const float* __restrict__ e_amo,
    const float* __restrict__ e_awd, const float* __restrict__ e_ahr,
    const float* __restrict__ e_mw,  const float* __restrict__ e_mi,
    const float* __restrict__ e_mmo, const float* __restrict__ e_mwd,
    const float* __restrict__ e_mhr,
    const float* __restrict__ Wxa,   const float* __restrict__ Wxm,
    const float* __restrict__ Wua,   const float* __restrict__ Wum,
    const float* __restrict__ a_aa,  const float* __restrict__ a_am,
    const float* __restrict__ a_ma,  const float* __restrict__ a_mm,
    const float* __restrict__ gaw_ih, const float* __restrict__ gaw_hh,
    const float* __restrict__ gab_ih, const float* __restrict__ gab_hh,
    const float* __restrict__ gmw_ih, const float* __restrict__ gmw_hh,
    const float* __restrict__ gmb_ih, const float* __restrict__ gmb_hh,
    const int* __restrict__ Xa_ex,   const int* __restrict__ Xm_ex,
    float* __restrict__ out)
{
    extern __shared__ char smraw[];
    SM& s = *reinterpret_cast<SM*>(smraw);

    const int tid  = threadIdx.x;
    const int b    = blockIdx.x;
    const int lane = tid & 31;
    const int wid  = tid >> 5;

    // ---------- one-time setup ----------
    for (int i = tid; i < 6*HH;  i += THREADS) s.Wxa[i] = Wxa[i];
    for (int i = tid; i < 4*HH;  i += THREADS) s.Wxm[i] = Wxm[i];
    for (int i = tid; i < 14*HH; i += THREADS) { s.Wua[i] = Wua[i]; s.Wum[i] = Wum[i]; }
    // GRU weights transposed [k][gate]; dest-indexed (conflict-free stores)
    for (int i = tid; i < 96*HH; i += THREADS) {
        int k = i / 96, g = i % 96;
        s.wihT_a[i] = gaw_ih[g*HH+k]; s.whhT_a[i] = gaw_hh[g*HH+k];
        s.wihT_m[i] = gmw_ih[g*HH+k]; s.whhT_m[i] = gmw_hh[g*HH+k];
    }
    for (int i = tid; i < 96; i += THREADS) {
        s.bih_a[i] = gab_ih[i]; s.bhh_a[i] = gab_hh[i];
        s.bih_m[i] = gmb_ih[i]; s.bhh_m[i] = gmb_hh[i];
    }
    for (int i = tid; i < 4*HH; i += THREADS) {
        int c = i >> 5, k = i & 31;
        const float* a = (c==0)?a_aa:(c==1)?a_am:(c==2)?a_ma:a_mm;
        s.a_src[c][k] = a[k];
        s.a_dst[c][k] = a[92+k];
    }
    if (tid < 4) {
        const float* a = (tid==0)?a_aa:(tid==1)?a_am:(tid==2)?a_ma:a_mm;
        s.a_last[tid] = a[184];
    }
    for (int i = tid; i < 70; i += THREADS) s.emb_aqi[i]      = e_ai[i];
    for (int i = tid; i < 26; i += THREADS) s.emb_aqi[70+i]   = e_amo[i];
    for (int i = tid; i < 14; i += THREADS) s.emb_aqi[96+i]   = e_awd[i];
    for (int i = tid; i < 48; i += THREADS) s.emb_aqi[110+i]  = e_ahr[i];
    for (int i = tid; i < 18; i += THREADS) s.emb_meo[i]      = e_mw[i];
    for (int i = tid; i < 36; i += THREADS) s.emb_meo[18+i]   = e_mi[i];
    for (int i = tid; i < 26; i += THREADS) s.emb_meo[54+i]   = e_mmo[i];
    for (int i = tid; i < 14; i += THREADS) s.emb_meo[80+i]   = e_mwd[i];
    for (int i = tid; i < 48; i += THREADS) s.emb_meo[94+i]   = e_mhr[i];
    for (int i = tid; i < HH*WD; i += THREADS) s.h_T[i] = 0.f;
    for (int i = tid; i < 6*WD; i += THREADS) s.xT[i] = 0.f;
    if (tid < 8) s.attT[NN*SW + tid] = 0.f;
    __syncthreads();

    // context dots (role x node), once
    for (int p = tid; p < 4*NN; p += THREADS) {
        int n = p % NN, role = p / NN;
        int c;
        if (role == 0)      c = (n<NAq)?0:2;
        else if (role == 1) c = (n<NAq)?1:3;
        else if (role == 2) c = (n<NAq)?0:1;
        else                c = (n<NAq)?2:3;
        const float* a = (c==0)?a_aa:(c==1)?a_am:(c==2)?a_ma:a_mm;
        const float* w = (role < 2) ? (a + 32) : (a + 124);
        float acc = 0.f;
        #pragma unroll 4
        for (int k = 0; k < CTXD; k++) acc += ctx[n*CTXD+k]*w[k];
        if (role == 0)      s.ctxsA[n] = acc;
        else if (role == 1) s.ctxsM[n] = acc;
        else if (role == 2) s.ctxdA[n] = acc;
        else                s.ctxdM[n] = acc;
    }
    __syncthreads();
    for (int p = tid; p < NN*NN; p += THREADS) {
        int j = p / NN, i = p % NN;
        int c = ((i < NAq) ? 0 : 2) + ((j < NAq) ? 0 : 1);
        float v = (adj[i*NN+j] > 0.f) ? adjn[i*NN+j]*s.a_last[c] : -1e30f;
        s.baseT[j*SW + CN(i)] = v;
    }
    __syncthreads();

    const int  cn0 = wid * 8;          // this warp's 8-column tile
    const bool isA = (wid < 5);
    const float* WI = isA ? s.wihT_a : s.wihT_m;
    const float* WH = isA ? s.whhT_a : s.whhT_m;
    const float* BI = isA ? s.bih_a  : s.bih_m;
    const float* BH = isA ? s.bhh_a  : s.bhh_m;
    const float b_ir = BI[lane], b_iz = BI[32+lane], b_in = BI[64+lane];
    const float b_hr = BH[lane], b_hz = BH[32+lane], b_hn = BH[64+lane];

    // ---------- timestep loop ----------
    for (int t = 0; t < TT; t++) {
        // p0: load + transpose raw features
        {
            const float* gx = X_aqi + (size_t)(b*TT + t)*NAq*6;
            for (int i = tid; i < NAq*6; i += THREADS) {
                int n = i/6, k = i%6;
                s.xT[k*WD + n] = gx[i];
            }
            const float* gm = X_meo + (size_t)(b*TT + t)*NMe*4;
            for (int i = tid; i < NMe*4; i += THREADS) {
                int m = i/4, k = i%4;
                s.xT[k*WD + 40 + m] = gm[i];
            }
            const int* ga = Xa_ex + (size_t)(b*TT + t)*NAq*4;
            for (int i = tid; i < NAq*4; i += THREADS) s.exa[i] = ga[i];
            const int* gme = Xm_ex + (size_t)(b*TT + t)*NMe*5;
            for (int i = tid; i < NMe*5; i += THREADS) s.exm[i] = gme[i];
        }
        __syncthreads();

        // p1: attri + featf, one 8-node tile per warp, f32x2 packed
        {
            u64 av[4] = {0,0,0,0}, fv[4] = {0,0,0,0};
            if (isA) {
                #pragma unroll
                for (int k = 0; k < 6; k++) {
                    ulonglong2 xa = *(const ulonglong2*)(s.xT + k*WD + cn0);
                    ulonglong2 xb = *(const ulonglong2*)(s.xT + k*WD + cn0 + 4);
                    u64 wa = dup2(s.Wxa[k*HH+lane]);
                    u64 wu = dup2(s.Wua[k*HH+lane]);
                    fma2(av[0], xa.x, wa); fma2(av[1], xa.y, wa);
                    fma2(av[2], xb.x, wa); fma2(av[3], xb.y, wa);
                    fma2(fv[0], xa.x, wu); fma2(fv[1], xa.y, wu);
                    fma2(fv[2], xb.x, wu); fma2(fv[3], xb.y, wu);
                }
                const int offs[4] = {0, 35, 48, 55};
                #pragma unroll
                for (int e = 0; e < 4; e++) {
                    u64 wA = dup2(s.Wua[(6+2*e)*HH+lane]);
                    u64 wB = dup2(s.Wua[(7+2*e)*HH+lane]);
                    #pragma unroll
                    for (int pr = 0; pr < 4; pr++) {
                        int n0 = cn0 + 2*pr, n1 = n0 + 1;
                        int i0 = (n0 < NAq) ? s.exa[n0*4+e] : 0;
                        int i1 = (n1 < NAq) ? s.exa[n1*4+e] : 0;
                        float2 em0 = *(const float2*)(s.emb_aqi + (offs[e]+i0)*2);
                        float2 em1 = *(const float2*)(s.emb_aqi + (offs[e]+i1)*2);
                        fma2(fv[pr], pk2(em0.x, em1.x), wA);
                        fma2(fv[pr], pk2(em0.y, em1.y), wB);
                    }
                }
                #pragma unroll
                for (int pr = 0; pr < 4; pr++) {
                    float2 a2 = up2(av[pr]);
                    int n0 = cn0 + 2*pr;
                    if (n0   < NAq) s.attri[n0*HH + lane]     = a2.x;
                    if (n0+1 < NAq) s.attri[(n0+1)*HH + lane] = a2.y;
                }
            } else {
                #pragma unroll
                for (int k = 0; k < 4; k++) {
                    ulonglong2 xa = *(const ulonglong2*)(s.xT + k*WD + cn0);
                    ulonglong2 xb = *(const ulonglong2*)(s.xT + k*WD + cn0 + 4);
                    u64 wa = dup2(s.Wxm[k*HH+lane]);
                    u64 wu = dup2(s.Wum[k*HH+lane]);
                    fma2(av[0], xa.x, wa); fma2(av[1], xa.y, wa);
                    fma2(av[2], xb.x, wa); fma2(av[3], xb.y, wa);
                    fma2(fv[0], xa.x, wu); fma2(fv[1], xa.y, wu);
                    fma2(fv[2], xb.x, wu); fma2(fv[3], xb.y, wu);
                }
                const int offs[5] = {0, 9, 27, 40, 47};
                #pragma unroll
                for (int e = 0; e < 5; e++) {
                    u64 wA = dup2(s.Wum[(4+2*e)*HH+lane]);
                    u64 wB = dup2(s.Wum[(5+2*e)*HH+lane]);
                    #pragma unroll
                    for (int pr = 0; pr < 4; pr++) {
                        int c0 = cn0 + 2*pr, c1 = c0 + 1;
                        int i0 = (c0 <= 57) ? s.exm[(c0-40)*5+e] : 0;
                        int i1 = (c1 <= 57) ? s.exm[(c1-40)*5+e] : 0;
                        float2 em0 = *(const float2*)(s.emb_meo + (offs[e]+i0)*2);
                        float2 em1 = *(const float2*)(s.emb_meo + (offs[e]+i1)*2);
                        fma2(fv[pr], pk2(em0.x, em1.x), wA);
                        fma2(fv[pr], pk2(em0.y, em1.y), wB);
                    }
                }
                #pragma unroll
                for (int pr = 0; pr < 4; pr++) {
                    float2 a2 = up2(av[pr]);
                    int c0 = cn0 + 2*pr;
                    if (c0   <= 57) s.attri[(c0-5)*HH + lane] = a2.x;
                    if (c0+1 <= 57) s.attri[(c0-4)*HH + lane] = a2.y;
                }
            }
            *(ulonglong2*)(s.gat_T + lane*WD + cn0)     = make_ulonglong2(fv[0], fv[1]);
            *(ulonglong2*)(s.gat_T + lane*WD + cn0 + 4) = make_ulonglong2(fv[2], fv[3]);
        }
        __syncthreads();

        // p2: src/dst projections (role x column)
        {
            int role = tid >> 6, q = tid & 63;
            bool valid = (q < NAq) || (q >= 40 && q < 58);
            int n = (q < NAq) ? q : q - 5;
            int c; float acc; const float* w;
            bool nA = q < NAq;
            if (role == 0)      { c = nA?0:2; w = s.a_src[c]; acc = valid ? s.ctxsA[n] : 0.f; }
            else if (role == 1) { c = nA?1:3; w = s.a_src[c]; acc = valid ? s.ctxsM[n] : 0.f; }
            else if (role == 2) { c = nA?0:1; w = s.a_dst[c]; acc = valid ? s.ctxdA[n] : 0.f; }
            else                { c = nA?2:3; w = s.a_dst[c]; acc = valid ? s.ctxdM[n] : 0.f; }
            #pragma unroll 8
            for (int k = 0; k < HH; k++) acc += s.gat_T[k*WD + q] * w[k];
            if (valid) {
                if (role == 0)      s.srcA[n] = acc;
                else if (role == 1) s.srcM[n] = acc;
                else if (role == 2) s.dstA[n] = acc;
                else                s.dstM[n] = acc;
            }
        }
        __syncthreads();

        // p3/4: logits + exp + sum, quad of threads per column (max-free, clamped)
        {
            int cn = tid >> 2, sub = tid & 3;
            bool valid = (cn < NAq) || (cn >= 40 && cn < 58);
            float sum = 0.f;
            if (valid) {
                int i = (cn < NAq) ? cn : cn - 5;
                float sAv = s.srcA[i], sMv = s.srcM[i];
                const float* dp = (i < NAq) ? s.dstA : s.dstM;
                for (int j = sub; j < NN; j += 4) {
                    float x = ((j < NAq) ? sAv : sMv) + dp[j] + s.baseT[j*SW+cn];
                    x = (x >= 0.f) ? x : 0.2f*x;
                    float v = __expf(fminf(x, 60.f));
                    s.attT[j*SW+cn] = v;
                    sum += v;
                }
            } else if (cn < SW) {
                for (int j = sub; j < NN; j += 4) s.attT[j*SW+cn] = 0.f;
            }
            sum += __shfl_xor_sync(0xffffffffu, sum, 1);
            sum += __shfl_xor_sync(0xffffffffu, sum, 2);
            if (sub == 0) s.inv[cn] = valid ? __fdividef(1.f, sum) : 0.f;
        }
        __syncthreads();

        // p5: GAT output (att @ attri, f32x2), same-warp tile — then fused GRU
        {
            u64 acc[4] = {0,0,0,0};
            #pragma unroll 4
            for (int j = 0; j < NN; j++) {
                u64 ap = dup2(s.attri[j*HH + lane]);
                ulonglong2 t0 = *(const ulonglong2*)(s.attT + j*SW + cn0);
                ulonglong2 t1 = *(const ulonglong2*)(s.attT + j*SW + cn0 + 4);
                fma2(acc[0], t0.x, ap); fma2(acc[1], t0.y, ap);
                fma2(acc[2], t1.x, ap); fma2(acc[3], t1.y, ap);
            }
            float4 iv0 = *(const float4*)(s.inv + cn0);
            float4 iv1 = *(const float4*)(s.inv + cn0 + 4);
            acc[0] = mul2(acc[0], pk2(iv0.x, iv0.y));
            acc[1] = mul2(acc[1], pk2(iv0.z, iv0.w));
            acc[2] = mul2(acc[2], pk2(iv1.x, iv1.y));
            acc[3] = mul2(acc[3], pk2(iv1.z, iv1.w));
            *(ulonglong2*)(s.gat_T + lane*WD + cn0)     = make_ulonglong2(acc[0], acc[1]);
            *(ulonglong2*)(s.gat_T + lane*WD + cn0 + 4) = make_ulonglong2(acc[2], acc[3]);
        }
        __syncwarp();

        // p6: GRU, same tile, f32x2 packed
        {
            u64 gr[4]={0,0,0,0}, gz[4]={0,0,0,0}, gn[4]={0,0,0,0};
            u64 hr[4]={0,0,0,0}, hz[4]={0,0,0,0}, hn[4]={0,0,0,0};
            #pragma unroll 4
            for (int k = 0; k < HH; k++) {
                ulonglong2 x0 = *(const ulonglong2*)(s.gat_T + k*WD + cn0);
                ulonglong2 x1 = *(const ulonglong2*)(s.gat_T + k*WD + cn0 + 4);
                ulonglong2 h0 = *(const ulonglong2*)(s.h_T  + k*WD + cn0);
                ulonglong2 h1 = *(const ulonglong2*)(s.h_T  + k*WD + cn0 + 4);
                u64 w0 = dup2(WI[k*96 + lane]);
                u64 w1 = dup2(WI[k*96 + 32 + lane]);
                u64 w2 = dup2(WI[k*96 + 64 + lane]);
                u64 v0 = dup2(WH[k*96 + lane]);
                u64 v1 = dup2(WH[k*96 + 32 + lane]);
                u64 v2 = dup2(WH[k*96 + 64 + lane]);
                fma2(gr[0], x0.x, w0); fma2(gr[1], x0.y, w0);
                fma2(gr[2], x1.x, w0); fma2(gr[3], x1.y, w0);
                fma2(gz[0], x0.x, w1); fma2(gz[1], x0.y, w1);
                fma2(gz[2], x1.x, w1); fma2(gz[3], x1.y, w1);
                fma2(gn[0], x0.x, w2); fma2(gn[1], x0.y, w2);
                fma2(gn[2], x1.x, w2); fma2(gn[3], x1.y, w2);
                fma2(hr[0], h0.x, v0); fma2(hr[1], h0.y, v0);
                fma2(hr[2], h1.x, v0); fma2(hr[3], h1.y, v0);
                fma2(hz[0], h0.x, v1); fma2(hz[1], h0.y, v1);
                fma2(hz[2], h1.x, v1); fma2(hz[3], h1.y, v1);
                fma2(hn[0], h0.x, v2); fma2(hn[1], h0.y, v2);
                fma2(hn[2], h1.x, v2); fma2(hn[3], h1.y, v2);
            }
            ulonglong2 ho0 = *(const ulonglong2*)(s.h_T + lane*WD + cn0);
            ulonglong2 ho1 = *(const ulonglong2*)(s.h_T + lane*WD + cn0 + 4);
            u64 hop[4] = {ho0.x, ho0.y, ho1.x, ho1.y};
            u64 res[4];
            #pragma unroll
            for (int p = 0; p < 4; p++) {
                float2 R = up2(gr[p]), Z = up2(gz[p]), Nn = up2(gn[p]);
                float2 HR = up2(hr[p]), HZ = up2(hz[p]), HN = up2(hn[p]);
                float2 HO = up2(hop[p]);
                float r0 = sigf(R.x + b_ir + HR.x + b_hr);
                float z0 = sigf(Z.x + b_iz + HZ.x + b_hz);
                float n0 = tanhf_fast(Nn.x + b_in + r0*(HN.x + b_hn));
                float o0 = (1.f - z0)*n0 + z0*HO.x;
                float r1 = sigf(R.y + b_ir + HR.y + b_hr);
                float z1 = sigf(Z.y + b_iz + HZ.y + b_hz);
                float n1 = tanhf_fast(Nn.y + b_in + r1*(HN.y + b_hn));
                float o1 = (1.f - z1)*n1 + z1*HO.y;
                res[p] = pk2(o0, o1);
            }
            __syncwarp();
            *(ulonglong2*)(s.h_T + lane*WD + cn0)     = make_ulonglong2(res[0], res[1]);
            *(ulonglong2*)(s.h_T + lane*WD + cn0 + 4) = make_ulonglong2(res[2], res[3]);
        }
        __syncthreads();
    }

    // ---------- output ----------
    for (int p = tid; p < NN*HH; p += THREADS) {
        int n = p >> 5, hd = p & 31;
        float v = s.h_T[hd*WD + CN(n)];
        if (n < NAq) out[((size_t)b*NAq + n)*HH + hd] = v;
        else         out[(size_t)NB*NAq*HH + ((size_t)b*NMe + (n-NAq))*HH + hd] = v;
    }
}

extern "C" void kernel_launch(void* const* d_in, const int* in_sizes, int n_in,
                              void* d_out, int out_size)
{
    (void)in_sizes; (void)n_in; (void)out_size;
    cudaFuncSetAttribute(chgat_gru_kernel,
                         cudaFuncAttributeMaxDynamicSharedMemorySize,
                         (int)sizeof(SM));
    chgat_gru_kernel<<<NB, THREADS, sizeof(SM)>>>(
        (const float*)d_in[0],  (const float*)d_in[1],
        (const float*)d_in[2],  (const float*)d_in[3],
        (const float*)d_in[4],
        (const float*)d_in[5],  (const float*)d_in[6],
        (const float*)d_in[7],  (const float*)d_in[8],
        (const float*)d_in[9],  (const float*)d_in[10],
        (const float*)d_in[11], (const float*)d_in[12],
        (const float*)d_in[13],
        (const float*)d_in[14], (const float*)d_in[15],
        (const float*)d_in[16], (const float*)d_in[17],
        (const float*)d_in[18], (const float*)d_in[19],
        (const float*)d_in[20], (const float*)d_in[21],
        (const float*)d_in[22], (const float*)d_in[23],
        (const float*)d_in[24], (const float*)d_in[25],
        (const float*)d_in[26], (const float*)d_in[27],
        (const float*)d_in[28], (const float*)d_in[29],
        (const int*)d_in[30],   (const int*)d_in[31],
        (float*)d_out);
}

// round 7
// speedup vs baseline: 2.5217x; 1.1373x over previous
#include <cuda_runtime.h>

#define NB   1024
#define TT   48
#define NAq  35
#define NMe  18
#define NN   53
#define HH   32
#define CTXD 60
#define THREADS 256
#define WX   64     // xT row stride
#define WD2  68     // h_T / gat_T row stride (68/4=17 odd -> conflict-free lane-strided f4)
#define SW   60     // attT/baseT row stride
#define GS   36     // GRU weight row stride ([gate][k] padded)

#define CN(n) ((n) < NAq ? (n) : (n) + 5)

typedef unsigned long long u64;

__device__ float g_baseT[NN*SW];

struct __align__(16) SM {
    float attT[NN*SW + 8];      // +8 tail pad: tile-7 float4 overflow at j=52
    float h_T[HH*WD2];          // [hd][cn]
    float gat_T[HH*WD2];        // [hd][cn] featf then GAT output
    float xT[6*WX];             // [k][cn]
    float inv[WX];
    float wih_a[96*GS], whh_a[96*GS], wih_m[96*GS], whh_m[96*GS]; // [gate][k] pad GS
    float Wxa[6*HH], Wxm[4*HH], Wua[14*HH], Wum[14*HH];
    float a_src[4][HH], a_dst[4][HH];
    float bih_a[96], bhh_a[96], bih_m[96], bhh_m[96];
    float emb_aqi[158];
    float emb_meo[142];
    float attri[NN*HH];         // [node][hd]
    float srcA[NN], srcM[NN], dstA[NN], dstM[NN];
    float ctxsA[NN], ctxsM[NN], ctxdA[NN], ctxdM[NN];
    int   exa[NAq*4];
    int   exm[NMe*5];
};

__device__ __forceinline__ u64 pk2(float lo, float hi) {
    u64 r; asm("mov.b64 %0,{%1,%2};" : "=l"(r) : "f"(lo), "f"(hi)); return r;
}
__device__ __forceinline__ u64 dup2(float v) { return pk2(v, v); }
__device__ __forceinline__ float2 up2(u64 a) {
    float2 r; asm("mov.b64 {%0,%1},%2;" : "=f"(r.x), "=f"(r.y) : "l"(a)); return r;
}
__device__ __forceinline__ void fma2(u64& d, u64 a, u64 b) {
    asm("fma.rn.f32x2 %0,%1,%2,%0;" : "+l"(d) : "l"(a), "l"(b));
}
__device__ __forceinline__ u64 mul2(u64 a, u64 b) {
    u64 r; asm("mul.rn.f32x2 %0,%1,%2;" : "=l"(r) : "l"(a), "l"(b)); return r;
}
__device__ __forceinline__ float sigf(float x) {
    return __fdividef(1.f, 1.f + __expf(-x));
}
__device__ __forceinline__ float tanhf_fast(float x) {
    return 2.f * sigf(2.f * x) - 1.f;
}

// ---- pre-kernel: build CTA-invariant mask-folded base matrix in global ----
__global__ void base_kernel(const float* __restrict__ adj, const float* __restrict__ adjn,
                            const float* __restrict__ a_aa, const float* __restrict__ a_am,
                            const float* __restrict__ a_ma, const float* __restrict__ a_mm)
{
    float aL[4] = {a_aa[184], a_am[184], a_ma[184], a_mm[184]};
    for (int p = threadIdx.x; p < NN*SW; p += blockDim.x) {
        int j = p / SW, cn = p % SW;
        bool valid = (cn < NAq) || (cn >= 40 && cn < 58);
        float v = -1e30f;
        if (valid) {
            int i = (cn < NAq) ? cn : cn - 5;
            int c = ((i < NAq) ? 0 : 2) + ((j < NAq) ? 0 : 1);
            v = (adj[i*NN+j] > 0.f) ? adjn[i*NN+j]*aL[c] : -1e30f;
        }
        g_baseT[p] = v;
    }
}

__global__ __launch_bounds__(THREADS, 2)
void chgat_gru_kernel(
    const float* __restrict__ X_aqi, const float* __restrict__ X_meo,
    const float* __restrict__ ctx,
    const float* __restrict__ e_ai,  const float* __restrict__ e_amo,
    const float* __restrict__ e_awd, const float* __restrict__ e_ahr,
    const float* __restrict__ e_mw,  const float* __restrict__ e_mi,
    const float* __restrict__ e_mmo, const float* __restrict__ e_mwd,
    const float* __restrict__ e_mhr,
    const float* __restrict__ Wxa,   const float* __restrict__ Wxm,
    const float* __restrict__ Wua,   const float* __restrict__ Wum,
    const float* __restrict__ a_aa,  const float* __restrict__ a_am,
    const float* __restrict__ a_ma,  const float* __restrict__ a_mm,
    const float* __restrict__ gaw_ih, const float* __restrict__ gaw_hh,
    const float* __restrict__ gab_ih, const float* __restrict__ gab_hh,
    const float* __restrict__ gmw_ih, const float* __restrict__ gmw_hh,
    const float* __restrict__ gmb_ih, const float* __restrict__ gmb_hh,
    const int* __restrict__ Xa_ex,   const int* __restrict__ Xm_ex,
    float* __restrict__ out)
{
    extern __shared__ char smraw[];
    SM& s = *reinterpret_cast<SM*>(smraw);

    const int tid  = threadIdx.x;
    const int b    = blockIdx.x;
    const int lane = tid & 31;
    const int wid  = tid >> 5;

    // ---------- one-time setup ----------
    for (int i = tid; i < 6*HH;  i += THREADS) s.Wxa[i] = Wxa[i];
    for (int i = tid; i < 4*HH;  i += THREADS) s.Wxm[i] = Wxm[i];
    for (int i = tid; i < 14*HH; i += THREADS) { s.Wua[i] = Wua[i]; s.Wum[i] = Wum[i]; }
    // GRU weights [gate][k] padded to GS
    for (int i = tid; i < 96*HH; i += THREADS) {
        int g = i >> 5, k = i & 31;
        s.wih_a[g*GS+k] = gaw_ih[i]; s.whh_a[g*GS+k] = gaw_hh[i];
        s.wih_m[g*GS+k] = gmw_ih[i]; s.whh_m[g*GS+k] = gmw_hh[i];
    }
    for (int i = tid; i < 96; i += THREADS) {
        s.bih_a[i] = gab_ih[i]; s.bhh_a[i] = gab_hh[i];
        s.bih_m[i] = gmb_ih[i]; s.bhh_m[i] = gmb_hh[i];
    }
    for (int i = tid; i < 4*HH; i += THREADS) {
        int c = i >> 5, k = i & 31;
        const float* a = (c==0)?a_aa:(c==1)?a_am:(c==2)?a_ma:a_mm;
        s.a_src[c][k] = a[k];
        s.a_dst[c][k] = a[92+k];
    }
    for (int i = tid; i < 70; i += THREADS) s.emb_aqi[i]      = e_ai[i];
    for (int i = tid; i < 26; i += THREADS) s.emb_aqi[70+i]   = e_amo[i];
    for (int i = tid; i < 14; i += THREADS) s.emb_aqi[96+i]   = e_awd[i];
    for (int i = tid; i < 48; i += THREADS) s.emb_aqi[110+i]  = e_ahr[i];
    for (int i = tid; i < 18; i += THREADS) s.emb_meo[i]      = e_mw[i];
    for (int i = tid; i < 36; i += THREADS) s.emb_meo[18+i]   = e_mi[i];
    for (int i = tid; i < 26; i += THREADS) s.emb_meo[54+i]   = e_mmo[i];
    for (int i = tid; i < 14; i += THREADS) s.emb_meo[80+i]   = e_mwd[i];
    for (int i = tid; i < 48; i += THREADS) s.emb_meo[94+i]   = e_mhr[i];
    for (int i = tid; i < HH*WD2; i += THREADS) s.h_T[i] = 0.f;
    for (int i = tid; i < 6*WX; i += THREADS) s.xT[i] = 0.f;
    if (tid < 8) s.attT[NN*SW + tid] = 0.f;
    __syncthreads();

    // context dots (role x node), once
    for (int p = tid; p < 4*NN; p += THREADS) {
        int n = p % NN, role = p / NN;
        int c;
        if (role == 0)      c = (n<NAq)?0:2;
        else if (role == 1) c = (n<NAq)?1:3;
        else if (role == 2) c = (n<NAq)?0:1;
        else                c = (n<NAq)?2:3;
        const float* a = (c==0)?a_aa:(c==1)?a_am:(c==2)?a_ma:a_mm;
        const float* w = (role < 2) ? (a + 32) : (a + 124);
        float acc = 0.f;
        #pragma unroll 4
        for (int k = 0; k < CTXD; k++) acc += ctx[n*CTXD+k]*w[k];
        if (role == 0)      s.ctxsA[n] = acc;
        else if (role == 1) s.ctxsM[n] = acc;
        else if (role == 2) s.ctxdA[n] = acc;
        else                s.ctxdM[n] = acc;
    }
    __syncthreads();

    const int  cn0 = wid * 8;
    const bool isA = (wid < 5);
    const float* WI = isA ? s.wih_a : s.wih_m;
    const float* WH = isA ? s.whh_a : s.whh_m;
    const float* BI = isA ? s.bih_a : s.bih_m;
    const float* BH = isA ? s.bhh_a : s.bhh_m;
    const float b_ir = BI[lane], b_iz = BI[32+lane], b_in = BI[64+lane];
    const float b_hr = BH[lane], b_hz = BH[32+lane], b_hn = BH[64+lane];

    // ---------- timestep loop ----------
    for (int t = 0; t < TT; t++) {
        // p0: load + transpose raw features
        {
            const float* gx = X_aqi + (size_t)(b*TT + t)*NAq*6;
            for (int i = tid; i < NAq*6; i += THREADS) {
                int n = i/6, k = i%6;
                s.xT[k*WX + n] = gx[i];
            }
            const float* gm = X_meo + (size_t)(b*TT + t)*NMe*4;
            for (int i = tid; i < NMe*4; i += THREADS) {
                int m = i/4, k = i%4;
                s.xT[k*WX + 40 + m] = gm[i];
            }
            const int* ga = Xa_ex + (size_t)(b*TT + t)*NAq*4;
            for (int i = tid; i < NAq*4; i += THREADS) s.exa[i] = ga[i];
            const int* gme = Xm_ex + (size_t)(b*TT + t)*NMe*5;
            for (int i = tid; i < NMe*5; i += THREADS) s.exm[i] = gme[i];
        }
        __syncthreads();

        // p1: attri + featf, one 8-node tile per warp, f32x2 packed
        {
            u64 av[4] = {0,0,0,0}, fv[4] = {0,0,0,0};
            if (isA) {
                #pragma unroll
                for (int k = 0; k < 6; k++) {
                    ulonglong2 xa = *(const ulonglong2*)(s.xT + k*WX + cn0);
                    ulonglong2 xb = *(const ulonglong2*)(s.xT + k*WX + cn0 + 4);
                    u64 wa = dup2(s.Wxa[k*HH+lane]);
                    u64 wu = dup2(s.Wua[k*HH+lane]);
                    fma2(av[0], xa.x, wa); fma2(av[1], xa.y, wa);
                    fma2(av[2], xb.x, wa); fma2(av[3], xb.y, wa);
                    fma2(fv[0], xa.x, wu); fma2(fv[1], xa.y, wu);
                    fma2(fv[2], xb.x, wu); fma2(fv[3], xb.y, wu);
                }
                const int offs[4] = {0, 35, 48, 55};
                #pragma unroll
                for (int e = 0; e < 4; e++) {
                    u64 wA = dup2(s.Wua[(6+2*e)*HH+lane]);
                    u64 wB = dup2(s.Wua[(7+2*e)*HH+lane]);
                    #pragma unroll
                    for (int pr = 0; pr < 4; pr++) {
                        int n0 = cn0 + 2*pr, n1 = n0 + 1;
                        int i0 = (n0 < NAq) ? s.exa[n0*4+e] : 0;
                        int i1 = (n1 < NAq) ? s.exa[n1*4+e] : 0;
                        float2 em0 = *(const float2*)(s.emb_aqi + (offs[e]+i0)*2);
                        float2 em1 = *(const float2*)(s.emb_aqi + (offs[e]+i1)*2);
                        fma2(fv[pr], pk2(em0.x, em1.x), wA);
                        fma2(fv[pr], pk2(em0.y, em1.y), wB);
                    }
                }
                #pragma unroll
                for (int pr = 0; pr < 4; pr++) {
                    float2 a2 = up2(av[pr]);
                    int n0 = cn0 + 2*pr;
                    if (n0   < NAq) s.attri[n0*HH + lane]     = a2.x;
                    if (n0+1 < NAq) s.attri[(n0+1)*HH + lane] = a2.y;
                }
            } else {
                #pragma unroll
                for (int k = 0; k < 4; k++) {
                    ulonglong2 xa = *(const ulonglong2*)(s.xT + k*WX + cn0);
                    ulonglong2 xb = *(const ulonglong2*)(s.xT + k*WX + cn0 + 4);
                    u64 wa = dup2(s.Wxm[k*HH+lane]);
                    u64 wu = dup2(s.Wum[k*HH+lane]);
                    fma2(av[0], xa.x, wa); fma2(av[1], xa.y, wa);
                    fma2(av[2], xb.x, wa); fma2(av[3], xb.y, wa);
                    fma2(fv[0], xa.x, wu); fma2(fv[1], xa.y, wu);
                    fma2(fv[2], xb.x, wu); fma2(fv[3], xb.y, wu);
                }
                const int offs[5] = {0, 9, 27, 40, 47};
                #pragma unroll
                for (int e = 0; e < 5; e++) {
                    u64 wA = dup2(s.Wum[(4+2*e)*HH+lane]);
                    u64 wB = dup2(s.Wum[(5+2*e)*HH+lane]);
                    #pragma unroll
                    for (int pr = 0; pr < 4; pr++) {
                        int c0 = cn0 + 2*pr, c1 = c0 + 1;
                        int i0 = (c0 <= 57) ? s.exm[(c0-40)*5+e] : 0;
                        int i1 = (c1 <= 57) ? s.exm[(c1-40)*5+e] : 0;
                        float2 em0 = *(const float2*)(s.emb_meo + (offs[e]+i0)*2);
                        float2 em1 = *(const float2*)(s.emb_meo + (offs[e]+i1)*2);
                        fma2(fv[pr], pk2(em0.x, em1.x), wA);
                        fma2(fv[pr], pk2(em0.y, em1.y), wB);
                    }
                }
                #pragma unroll
                for (int pr = 0; pr < 4; pr++) {
                    float2 a2 = up2(av[pr]);
                    int c0 = cn0 + 2*pr;
                    if (c0   <= 57) s.attri[(c0-5)*HH + lane] = a2.x;
                    if (c0+1 <= 57) s.attri[(c0-4)*HH + lane] = a2.y;
                }
            }
            *(ulonglong2*)(s.gat_T + lane*WD2 + cn0)     = make_ulonglong2(fv[0], fv[1]);
            *(ulonglong2*)(s.gat_T + lane*WD2 + cn0 + 4) = make_ulonglong2(fv[2], fv[3]);
        }
        __syncthreads();

        // p2: src/dst projections (role x column)
        {
            int role = tid >> 6, q = tid & 63;
            bool valid = (q < NAq) || (q >= 40 && q < 58);
            int n = (q < NAq) ? q : q - 5;
            int c; float acc; const float* w;
            bool nA = q < NAq;
            if (role == 0)      { c = nA?0:2; w = s.a_src[c]; acc = valid ? s.ctxsA[n] : 0.f; }
            else if (role == 1) { c = nA?1:3; w = s.a_src[c]; acc = valid ? s.ctxsM[n] : 0.f; }
            else if (role == 2) { c = nA?0:1; w = s.a_dst[c]; acc = valid ? s.ctxdA[n] : 0.f; }
            else                { c = nA?2:3; w = s.a_dst[c]; acc = valid ? s.ctxdM[n] : 0.f; }
            #pragma unroll 8
            for (int k = 0; k < HH; k++) acc += s.gat_T[k*WD2 + (q < 58 ? q : 0)] * w[k];
            if (valid) {
                if (role == 0)      s.srcA[n] = acc;
                else if (role == 1) s.srcM[n] = acc;
                else if (role == 2) s.dstA[n] = acc;
                else                s.dstM[n] = acc;
            }
        }
        __syncthreads();

        // p3/4: logits + exp + sum, quad per column; base from L1-cached global
        {
            int cn = tid >> 2, sub = tid & 3;
            bool valid = (cn < NAq) || (cn >= 40 && cn < 58);
            float sum = 0.f;
            if (valid) {
                int i = (cn < NAq) ? cn : cn - 5;
                float sAv = s.srcA[i], sMv = s.srcM[i];
                const float* dp = (i < NAq) ? s.dstA : s.dstM;
                for (int j = sub; j < NN; j += 4) {
                    float x = ((j < NAq) ? sAv : sMv) + dp[j] + __ldg(g_baseT + j*SW + cn);
                    x = (x >= 0.f) ? x : 0.2f*x;
                    float v = __expf(fminf(x, 60.f));
                    s.attT[j*SW+cn] = v;
                    sum += v;
                }
            } else if (cn < SW) {
                for (int j = sub; j < NN; j += 4) s.attT[j*SW+cn] = 0.f;
            }
            sum += __shfl_xor_sync(0xffffffffu, sum, 1);
            sum += __shfl_xor_sync(0xffffffffu, sum, 2);
            if (sub == 0 && cn < WX) s.inv[cn] = valid ? __fdividef(1.f, sum) : 0.f;
        }
        __syncthreads();

        // p5: GAT output (att @ attri, f32x2), same-warp tile
        {
            u64 acc[4] = {0,0,0,0};
            #pragma unroll 4
            for (int j = 0; j < NN; j++) {
                u64 ap = dup2(s.attri[j*HH + lane]);
                ulonglong2 t0 = *(const ulonglong2*)(s.attT + j*SW + cn0);
                ulonglong2 t1 = *(const ulonglong2*)(s.attT + j*SW + cn0 + 4);
                fma2(acc[0], t0.x, ap); fma2(acc[1], t0.y, ap);
                fma2(acc[2], t1.x, ap); fma2(acc[3], t1.y, ap);
            }
            float4 iv0 = *(const float4*)(s.inv + cn0);
            float4 iv1 = *(const float4*)(s.inv + cn0 + 4);
            acc[0] = mul2(acc[0], pk2(iv0.x, iv0.y));
            acc[1] = mul2(acc[1], pk2(iv0.z, iv0.w));
            acc[2] = mul2(acc[2], pk2(iv1.x, iv1.y));
            acc[3] = mul2(acc[3], pk2(iv1.z, iv1.w));
            *(ulonglong2*)(s.gat_T + lane*WD2 + cn0)     = make_ulonglong2(acc[0], acc[1]);
            *(ulonglong2*)(s.gat_T + lane*WD2 + cn0 + 4) = make_ulonglong2(acc[2], acc[3]);
        }
        __syncwarp();

        // p6: GRU, same tile, f32x2; weights via per-lane float4 rows
        {
            u64 gr[4]={0,0,0,0}, gz[4]={0,0,0,0}, gn[4]={0,0,0,0};
            u64 hr[4]={0,0,0,0}, hz[4]={0,0,0,0}, hn[4]={0,0,0,0};
            #pragma unroll
            for (int kc = 0; kc < 8; kc++) {
                float4 W0 = *(const float4*)(WI + lane*GS + 4*kc);
                float4 W1 = *(const float4*)(WI + (32+lane)*GS + 4*kc);
                float4 W2 = *(const float4*)(WI + (64+lane)*GS + 4*kc);
                float4 V0 = *(const float4*)(WH + lane*GS + 4*kc);
                float4 V1 = *(const float4*)(WH + (32+lane)*GS + 4*kc);
                float4 V2 = *(const float4*)(WH + (64+lane)*GS + 4*kc);
                const float* w0p = (const float*)&W0;
                const float* w1p = (const float*)&W1;
                const float* w2p = (const float*)&W2;
                const float* v0p = (const float*)&V0;
                const float* v1p = (const float*)&V1;
                const float* v2p = (const float*)&V2;
                #pragma unroll
                for (int kk = 0; kk < 4; kk++) {
                    int k = 4*kc + kk;
                    ulonglong2 x0 = *(const ulonglong2*)(s.gat_T + k*WD2 + cn0);
                    ulonglong2 x1 = *(const ulonglong2*)(s.gat_T + k*WD2 + cn0 + 4);
                    ulonglong2 h0 = *(const ulonglong2*)(s.h_T  + k*WD2 + cn0);
                    ulonglong2 h1 = *(const ulonglong2*)(s.h_T  + k*WD2 + cn0 + 4);
                    u64 w0 = dup2(w0p[kk]);
                    u64 w1 = dup2(w1p[kk]);
                    u64 w2 = dup2(w2p[kk]);
                    u64 v0 = dup2(v0p[kk]);
                    u64 v1 = dup2(v1p[kk]);
                    u64 v2 = dup2(v2p[kk]);
                    fma2(gr[0], x0.x, w0); fma2(gr[1], x0.y, w0);
                    fma2(gr[2], x1.x, w0); fma2(gr[3], x1.y, w0);
                    fma2(gz[0], x0.x, w1); fma2(gz[1], x0.y, w1);
                    fma2(gz[2], x1.x, w1); fma2(gz[3], x1.y, w1);
                    fma2(gn[0], x0.x, w2); fma2(gn[1], x0.y, w2);
                    fma2(gn[2], x1.x, w2); fma2(gn[3], x1.y, w2);
                    fma2(hr[0], h0.x, v0); fma2(hr[1], h0.y, v0);
                    fma2(hr[2], h1.x, v0); fma2(hr[3], h1.y, v0);
                    fma2(hz[0], h0.x, v1); fma2(hz[1], h0.y, v1);
                    fma2(hz[2], h1.x, v1); fma2(hz[3], h1.y, v1);
                    fma2(hn[0], h0.x, v2); fma2(hn[1], h0.y, v2);
                    fma2(hn[2], h1.x, v2); fma2(hn[3], h1.y, v2);
                }
            }
            ulonglong2 ho0 = *(const ulonglong2*)(s.h_T + lane*WD2 + cn0);
            ulonglong2 ho1 = *(const ulonglong2*)(s.h_T + lane*WD2 + cn0 + 4);
            u64 hop[4] = {ho0.x, ho0.y, ho1.x, ho1.y};
            u64 res[4];
            #pragma unroll
            for (int p = 0; p < 4; p++) {
                float2 R = up2(gr[p]), Z = up2(gz[p]), Nn = up2(gn[p]);
                float2 HR = up2(hr[p]), HZ = up2(hz[p]), HN = up2(hn[p]);
                float2 HO = up2(hop[p]);
                float r0 = sigf(R.x + b_ir + HR.x + b_hr);
                float z0 = sigf(Z.x + b_iz + HZ.x + b_hz);
                float n0 = tanhf_fast(Nn.x + b_in + r0*(HN.x + b_hn));
                float o0 = (1.f - z0)*n0 + z0*HO.x;
                float r1 = sigf(R.y + b_ir + HR.y + b_hr);
                float z1 = sigf(Z.y + b_iz + HZ.y + b_hz);
                float n1 = tanhf_fast(Nn.y + b_in + r1*(HN.y + b_hn));
                float o1 = (1.f - z1)*n1 + z1*HO.y;
                res[p] = pk2(o0, o1);
            }
            __syncwarp();
            *(ulonglong2*)(s.h_T + lane*WD2 + cn0)     = make_ulonglong2(res[0], res[1]);
            *(ulonglong2*)(s.h_T + lane*WD2 + cn0 + 4) = make_ulonglong2(res[2], res[3]);
        }
        __syncthreads();
    }

    // ---------- output ----------
    for (int p = tid; p < NN*HH; p += THREADS) {
        int n = p >> 5, hd = p & 31;
        float v = s.h_T[hd*WD2 + CN(n)];
        if (n < NAq) out[((size_t)b*NAq + n)*HH + hd] = v;
        else         out[(size_t)NB*NAq*HH + ((size_t)b*NMe + (n-NAq))*HH + hd] = v;
    }
}

extern "C" void kernel_launch(void* const* d_in, const int* in_sizes, int n_in,
                              void* d_out, int out_size)
{
    (void)in_sizes; (void)n_in; (void)out_size;
    base_kernel<<<1, 256>>>(
        (const float*)d_in[3],  (const float*)d_in[4],
        (const float*)d_in[18], (const float*)d_in[19],
        (const float*)d_in[20], (const float*)d_in[21]);
    cudaFuncSetAttribute(chgat_gru_kernel,
                         cudaFuncAttributeMaxDynamicSharedMemorySize,
                         (int)sizeof(SM));
    chgat_gru_kernel<<<NB, THREADS, sizeof(SM)>>>(
        (const float*)d_in[0],  (const float*)d_in[1],
        (const float*)d_in[2],
        (const float*)d_in[5],  (const float*)d_in[6],
        (const float*)d_in[7],  (const float*)d_in[8],
        (const float*)d_in[9],  (const float*)d_in[10],
        (const float*)d_in[11], (const float*)d_in[12],
        (const float*)d_in[13],
        (const float*)d_in[14], (const float*)d_in[15],
        (const float*)d_in[16], (const float*)d_in[17],
        (const float*)d_in[18], (const float*)d_in[19],
        (const float*)d_in[20], (const float*)d_in[21],
        (const float*)d_in[22], (const float*)d_in[23],
        (const float*)d_in[24], (const float*)d_in[25],
        (const float*)d_in[26], (const float*)d_in[27],
        (const float*)d_in[28], (const float*)d_in[29],
        (const int*)d_in[30],   (const int*)d_in[31],
        (float*)d_out);
}